// round 11
// baseline (speedup 1.0000x reference)
#include <cuda_runtime.h>
#include <math.h>

#define B_    8
#define M_    1026
#define NT_   1024
#define C_    384
#define H_    6
#define D_    64
#define HID_  1536
#define W_    256
#define CAT_  257
#define SCALE_ 0.4082482904638631f

// ---------------------------------------------------------------------------
// Scratch
// ---------------------------------------------------------------------------
__device__ float g_h1  [B_*M_*C_];
__device__ float g_qkv [B_*M_*3*C_];
__device__ float g_att [B_*M_*C_];
__device__ float g_res [B_*M_*C_];
__device__ float g_h2  [B_*(NT_+1)*C_];
__device__ float g_tok [B_*W_*C_];
__device__ float g_cat [B_*CAT_*C_];
__device__ float g_h3  [B_*CAT_*C_];
__device__ float g_fc1 [B_*CAT_*HID_];
__device__ float g_clsp[48*8*66];        // CLS split-K partials: m, s, o[64]
// precomputed sparse-attention key table
__device__ int   g_keys[NT_*32];         // float-offset (key*1152); 0 = CLS/filler
__device__ int   g_kcnt[NT_];

// ---------------------------------------------------------------------------
// Helpers
// ---------------------------------------------------------------------------
__device__ __forceinline__ float warpSum(float v) {
#pragma unroll
    for (int o = 16; o > 0; o >>= 1) v += __shfl_xor_sync(0xffffffffu, v, o);
    return v;
}
__device__ __forceinline__ float warpMax(float v) {
#pragma unroll
    for (int o = 16; o > 0; o >>= 1) v = fmaxf(v, __shfl_xor_sync(0xffffffffu, v, o));
    return v;
}
__device__ __forceinline__ unsigned f2tf(float f) {
    unsigned u;
    asm("cvt.rna.tf32.f32 %0, %1;" : "=r"(u) : "f"(f));
    return u;
}
__device__ __forceinline__ void cpasync16(void* smem_dst, const void* gsrc, bool pred) {
    unsigned saddr = (unsigned)__cvta_generic_to_shared(smem_dst);
    int sz = pred ? 16 : 0;
    asm volatile("cp.async.ca.shared.global [%0], [%1], 16, %2;\n"
                 :: "r"(saddr), "l"(gsrc), "r"(sz));
}

// ---------------------------------------------------------------------------
// Key table precompute: one block, 1024 threads (runs once per launch, ~2us)
// ---------------------------------------------------------------------------
__global__ void key_precompute_kernel() {
    int t = threadIdx.x;    // 0..1023
    int r = t >> 5, c = t & 31;
    int rl[5], cl[5];
    int nr = 0, nc = 0;
#pragma unroll
    for (int dr = -2; dr <= 2; ++dr) {
        int rp = r + dr;
        if (rp < 0 || rp > 31) continue;
        int lo = (r > rp ? r : rp) - 1; if (lo < 0) lo = 0;
        int hi = (r < rp ? r : rp) + 1; if (hi > 30) hi = 30;
        int fe = lo + (lo & 1);
        if (fe <= hi) rl[nr++] = rp;
    }
#pragma unroll
    for (int dc = -2; dc <= 2; ++dc) {
        int cp = c + dc;
        if (cp < 0 || cp > 31) continue;
        int lo = (c > cp ? c : cp) - 1; if (lo < 0) lo = 0;
        int hi = (c < cp ? c : cp) + 1; if (hi > 30) hi = 30;
        int fe = lo + (lo & 1);
        if (fe <= hi) cl[nc++] = cp;
    }
    int cnt = 1 + nr * nc;
    g_kcnt[t] = cnt;
    for (int j = 0; j < 32; ++j) {
        int key = 0;   // CLS row (also filler for invalid lanes)
        if (j >= 1 && j < cnt) {
            int i = j - 1;
            key = rl[i / nc] * 32 + cl[i % nc] + 1;
        }
        g_keys[t * 32 + j] = key * (3 * C_);   // float offset within batch
    }
}

// ---------------------------------------------------------------------------
// LayerNorm (round-3 exact)
// ---------------------------------------------------------------------------
__global__ void ln_kernel(const float* __restrict__ in, float* __restrict__ out,
                          const float* __restrict__ gw, const float* __restrict__ gb,
                          int inStride, int outStride) {
    int i = blockIdx.x, b = blockIdx.y;
    const float* xr = in + ((size_t)b * inStride + i) * C_;
    float* yr = out + ((size_t)b * outStride + i) * C_;
    int tid = threadIdx.x;
    float v0 = xr[tid], v1 = xr[tid + 128], v2 = xr[tid + 256];
    __shared__ float sm[4];
    float s = warpSum(v0 + v1 + v2);
    if ((tid & 31) == 0) sm[tid >> 5] = s;
    __syncthreads();
    float mu = (sm[0] + sm[1] + sm[2] + sm[3]) * (1.f / 384.f);
    float d0 = v0 - mu, d1 = v1 - mu, d2 = v2 - mu;
    __syncthreads();
    float q = warpSum(d0 * d0 + d1 * d1 + d2 * d2);
    if ((tid & 31) == 0) sm[tid >> 5] = q;
    __syncthreads();
    float var = (sm[0] + sm[1] + sm[2] + sm[3]) * (1.f / 384.f);
    float rs = rsqrtf(var + 1e-5f);
    yr[tid]       = d0 * rs * gw[tid]       + gb[tid];
    yr[tid + 128] = d1 * rs * gw[tid + 128] + gb[tid + 128];
    yr[tid + 256] = d2 * rs * gw[tid + 256] + gb[tid + 256];
}

__global__ void zero_pad_kernel() {
    g_h1[((size_t)blockIdx.x * M_ + 1025) * C_ + threadIdx.x] = 0.f;
}

// ---------------------------------------------------------------------------
// TF32 tensor-core GEMM (round-3/8 proven config): 128x64x32, 256 threads,
// 2-stage cp.async, warp tile 32x32 via m16n8k8.
// __launch_bounds__(256,4): force <=64 regs so 4 CTAs/SM fit (was 80 regs
// -> 3 CTAs -> occ 33.7%, every pipe half-idle).
// gatherMode: A row (b*256+w), col (kk*384+c) -> g_h2[b, hrow(w,kk), c].
// ---------------------------------------------------------------------------
#define KP_ 36
#define TG_SMEM ((2*128*KP_ + 2*64*KP_) * 4)   // 55296 bytes

__global__ void __launch_bounds__(256, 4)
tgemm_kernel(int M, int N, int K,
             const float* __restrict__ A, const float* __restrict__ Wt,
             const float* __restrict__ bias, const float* __restrict__ resid,
             float* __restrict__ Cc, int doGelu, int gatherMode) {
    extern __shared__ float dyn[];
    float (*sA)[128][KP_] = (float(*)[128][KP_])dyn;
    float (*sB)[64][KP_]  = (float(*)[64][KP_])(dyn + 2 * 128 * KP_);

    int tid  = threadIdx.x;
    int lane = tid & 31;
    int wid  = tid >> 5;
    int wm   = wid & 3;
    int wn   = wid >> 2;
    int lr   = lane >> 2;
    int lc   = lane & 3;

    int bm = blockIdx.y * 128;
    int bn = blockIdx.x * 64;

    int ldRow = tid >> 3;   // 0..31
    int ldC4  = tid & 7;    // 0..7

    float acc[2][4][4];
#pragma unroll
    for (int mt = 0; mt < 2; ++mt)
#pragma unroll
        for (int nt = 0; nt < 4; ++nt)
#pragma unroll
            for (int e = 0; e < 4; ++e) acc[mt][nt][e] = 0.f;

    int nIter = K >> 5;

    auto loadTile = [&](int it, int s) {
        int k0 = it << 5;
        if (!gatherMode) {
#pragma unroll
            for (int i = 0; i < 4; ++i) {
                int r = ldRow + i * 32;
                int gr = bm + r;
                bool p = gr < M;
                const float* src = A + (size_t)(p ? gr : 0) * K + k0 + ldC4 * 4;
                cpasync16(&sA[s][r][ldC4 * 4], src, p);
            }
        } else {
            int kk = k0 / 384;
            int c0 = k0 - kk * 384;
#pragma unroll
            for (int i = 0; i < 4; ++i) {
                int r = ldRow + i * 32;
                int gr = bm + r;
                int b = gr >> 8, w = gr & 255;
                int wi = w >> 4, wj = w & 15;
                int rr = 2 * wi + kk / 3 - 1;
                int cc = 2 * wj + kk % 3 - 1;
                int hrow = (rr < 0 || cc < 0) ? 1024 : rr * 32 + cc + 1;
                const float* src = A + ((size_t)b * 1025 + hrow) * 384 + c0 + ldC4 * 4;
                cpasync16(&sA[s][r][ldC4 * 4], src, true);
            }
        }
#pragma unroll
        for (int i = 0; i < 2; ++i) {
            int n = ldRow + i * 32;
            int gn = bn + n;
            bool p = gn < N;
            const float* src = Wt + (size_t)(p ? gn : 0) * K + k0 + ldC4 * 4;
            cpasync16(&sB[s][n][ldC4 * 4], src, p);
        }
    };

    loadTile(0, 0);
    asm volatile("cp.async.commit_group;\n");

    for (int it = 0; it < nIter; ++it) {
        int s = it & 1;
        if (it + 1 < nIter) {
            loadTile(it + 1, s ^ 1);
            asm volatile("cp.async.commit_group;\n");
            asm volatile("cp.async.wait_group 1;\n");
        } else {
            asm volatile("cp.async.wait_group 0;\n");
        }
        __syncthreads();

#pragma unroll
        for (int ks = 0; ks < 4; ++ks) {
            int kk = ks * 8;
            unsigned a[2][4], bf[4][2];
#pragma unroll
            for (int mt = 0; mt < 2; ++mt) {
                int row = wm * 32 + mt * 16 + lr;
                a[mt][0] = f2tf(sA[s][row    ][kk + lc]);
                a[mt][1] = f2tf(sA[s][row + 8][kk + lc]);
                a[mt][2] = f2tf(sA[s][row    ][kk + lc + 4]);
                a[mt][3] = f2tf(sA[s][row + 8][kk + lc + 4]);
            }
#pragma unroll
            for (int nt = 0; nt < 4; ++nt) {
                int n = wn * 32 + nt * 8 + lr;
                bf[nt][0] = f2tf(sB[s][n][kk + lc]);
                bf[nt][1] = f2tf(sB[s][n][kk + lc + 4]);
            }
#pragma unroll
            for (int mt = 0; mt < 2; ++mt)
#pragma unroll
                for (int nt = 0; nt < 4; ++nt) {
                    asm volatile(
                        "mma.sync.aligned.m16n8k8.row.col.f32.tf32.tf32.f32 "
                        "{%0,%1,%2,%3}, {%4,%5,%6,%7}, {%8,%9}, {%0,%1,%2,%3};\n"
                        : "+f"(acc[mt][nt][0]), "+f"(acc[mt][nt][1]),
                          "+f"(acc[mt][nt][2]), "+f"(acc[mt][nt][3])
                        : "r"(a[mt][0]), "r"(a[mt][1]), "r"(a[mt][2]), "r"(a[mt][3]),
                          "r"(bf[nt][0]), "r"(bf[nt][1]));
                }
        }
        __syncthreads();
    }

#pragma unroll
    for (int mt = 0; mt < 2; ++mt) {
#pragma unroll
        for (int nt = 0; nt < 4; ++nt) {
            int col = bn + wn * 32 + nt * 8 + 2 * lc;
            float bx = 0.f, by = 0.f;
            if (bias) { bx = bias[col]; by = bias[col + 1]; }
#pragma unroll
            for (int half = 0; half < 2; ++half) {
                int row = bm + wm * 32 + mt * 16 + lr + half * 8;
                if (row >= M) continue;
                float vx = acc[mt][nt][2 * half + 0] + bx;
                float vy = acc[mt][nt][2 * half + 1] + by;
                if (resid) {
                    const float2 rv = *(const float2*)(resid + (size_t)row * N + col);
                    vx += rv.x; vy += rv.y;
                }
                if (doGelu) {
                    vx = 0.5f * vx * (1.f + erff(vx * 0.70710678118654752f));
                    vy = 0.5f * vy * (1.f + erff(vy * 0.70710678118654752f));
                }
                *(float2*)(Cc + (size_t)row * N + col) = make_float2(vx, vy);
            }
        }
    }
}

// ---------------------------------------------------------------------------
// Sparse attention (token queries): one warp per (b,h,t), split-warp QK,
// precomputed key table (float offsets).
// ---------------------------------------------------------------------------
__global__ void attn_token_kernel() {
    int gw = (blockIdx.x * blockDim.x + threadIdx.x) >> 5;
    int lane = threadIdx.x & 31;
    int t  = gw & 1023;
    int bh = gw >> 10;
    int h = bh % H_;
    int b = bh / H_;

    int key_off = g_keys[t * 32 + lane];
    int cnt     = g_kcnt[t];

    const float* qp = g_qkv + ((size_t)b * M_ + (t + 1)) * (3 * C_) + h * D_;
    int hl = lane & 15;
    float4 qv = *(const float4*)(qp + hl * 4);
    const float* kbase = g_qkv + (size_t)b * M_ * (3 * C_) + C_ + h * D_;

    float s = -INFINITY;
    for (int j0 = 0; j0 < 26; j0 += 2) {
        if (j0 >= cnt) break;
        int ka = __shfl_sync(0xffffffffu, key_off, j0);
        int kb = __shfl_sync(0xffffffffu, key_off, j0 + 1);
        int kidx = (lane < 16) ? ka : kb;
        float4 kv = *(const float4*)(kbase + kidx + hl * 4);
        float d = qv.x * kv.x + qv.y * kv.y + qv.z * kv.z + qv.w * kv.w;
        d += __shfl_xor_sync(0xffffffffu, d, 8);
        d += __shfl_xor_sync(0xffffffffu, d, 4);
        d += __shfl_xor_sync(0xffffffffu, d, 2);
        d += __shfl_xor_sync(0xffffffffu, d, 1);
        float dx = __shfl_xor_sync(0xffffffffu, d, 16);
        float da = (lane < 16) ? d : dx;
        float db = (lane < 16) ? dx : d;
        if (lane == j0)     s = da * SCALE_;
        if (lane == j0 + 1) s = db * SCALE_;
    }
    if (lane >= cnt) s = -INFINITY;

    float m = fmaxf(warpMax(s), 0.f);
    float p = (lane < cnt) ? expf(s - m) : 0.f;
    float denom = warpSum(p) + expf(-m);
    float inv = 1.f / denom;

    const float* vbase = g_qkv + (size_t)b * M_ * (3 * C_) + 2 * C_ + h * D_;
    float o0 = 0.f, o1 = 0.f;
    for (int j = 0; j < cnt; ++j) {
        float pj = __shfl_sync(0xffffffffu, p, j);
        int   kj = __shfl_sync(0xffffffffu, key_off, j);
        float2 vv = *(const float2*)(vbase + kj + 2 * lane);
        o0 += pj * vv.x;
        o1 += pj * vv.y;
    }
    float* op = g_att + ((size_t)b * M_ + (t + 1)) * C_ + h * D_;
    *(float2*)(op + 2 * lane) = make_float2(o0 * inv, o1 * inv);
}

// ---------------------------------------------------------------------------
// CLS attention, split-K.
// ---------------------------------------------------------------------------
__global__ void attn_cls_part_kernel() {
    int chunk = blockIdx.x;          // 0..7
    int bh    = blockIdx.y;          // 0..47
    int b = bh / H_, h = bh % H_;
    int start = chunk * 129;
    int end   = start + 129; if (end > 1025) end = 1025;
    int cnt   = end - start;
    int tid = threadIdx.x;           // 128

    __shared__ float sq[64];
    __shared__ float sc[132];
    __shared__ float sred[4];
    __shared__ float oacc[128];

    const float* qp = g_qkv + (size_t)(b * M_) * (3 * C_) + h * D_;
    if (tid < 64) sq[tid] = qp[tid];
    __syncthreads();

    for (int j = tid; j < cnt; j += 128) {
        const float* kp = g_qkv + ((size_t)b * M_ + start + j) * (3 * C_) + C_ + h * D_;
        float acc = 0.f;
#pragma unroll
        for (int d0 = 0; d0 < D_; d0 += 4) {
            float4 kv = *(const float4*)(kp + d0);
            acc += sq[d0] * kv.x + sq[d0 + 1] * kv.y + sq[d0 + 2] * kv.z + sq[d0 + 3] * kv.w;
        }
        sc[j] = acc * SCALE_;
    }
    __syncthreads();

    float m = -INFINITY;
    for (int j = tid; j < cnt; j += 128) m = fmaxf(m, sc[j]);
    m = warpMax(m);
    if ((tid & 31) == 0) sred[tid >> 5] = m;
    __syncthreads();
    m = fmaxf(fmaxf(sred[0], sred[1]), fmaxf(sred[2], sred[3]));
    __syncthreads();

    float ls = 0.f;
    for (int j = tid; j < cnt; j += 128) {
        float pv = expf(sc[j] - m);
        sc[j] = pv;
        ls += pv;
    }
    ls = warpSum(ls);
    if ((tid & 31) == 0) sred[tid >> 5] = ls;
    __syncthreads();
    float ssum = sred[0] + sred[1] + sred[2] + sred[3];

    int d = tid & 63, grp = tid >> 6;
    float acc = 0.f;
    for (int j = grp; j < cnt; j += 2)
        acc += sc[j] * g_qkv[((size_t)b * M_ + start + j) * (3 * C_) + 2 * C_ + h * D_ + d];
    oacc[tid] = acc;
    __syncthreads();

    float* dst = g_clsp + ((size_t)bh * 8 + chunk) * 66;
    if (tid < 64) dst[2 + tid] = oacc[tid] + oacc[tid + 64];
    if (tid == 0) { dst[0] = m; dst[1] = ssum; }
}

__global__ void attn_cls_comb_kernel() {
    int bh = blockIdx.x;             // 0..47
    int b = bh / H_, h = bh % H_;
    int d = threadIdx.x;             // 64
    const float* src = g_clsp + (size_t)bh * 8 * 66;
    float M = 0.f;
#pragma unroll
    for (int c = 0; c < 8; ++c) M = fmaxf(M, src[c * 66]);
    float denom = expf(-M);
    float o = 0.f;
#pragma unroll
    for (int c = 0; c < 8; ++c) {
        float w = expf(src[c * 66] - M);
        denom += src[c * 66 + 1] * w;
        o += src[c * 66 + 2 + d] * w;
    }
    g_att[(size_t)(b * M_) * C_ + h * D_ + d] = o / denom;
}

// Pad query: parallel over rows. grid (12, B), block 256.
__global__ void attn_pad_kernel() {
    int b = blockIdx.y;
    int cg = blockIdx.x;
    int tid = threadIdx.x;
    int cl = tid & 31;
    int rg = tid >> 5;
    int ch = cg * 32 + cl;
    const float* base = g_qkv + (size_t)b * M_ * (3 * C_) + 2 * C_ + ch;
    float acc = 0.f;
    for (int mrow = rg; mrow < 1025; mrow += 8)
        acc += base[(size_t)mrow * (3 * C_)];
    __shared__ float sm2[8][32];
    sm2[rg][cl] = acc;
    __syncthreads();
    if (tid < 32) {
        float a = 0.f;
#pragma unroll
        for (int rr = 0; rr < 8; ++rr) a += sm2[rr][tid];
        g_att[((size_t)b * M_ + 1025) * C_ + cg * 32 + tid] = a * (1.0f / 1026.0f);
    }
}

__global__ void concat_kernel() {
    int row = blockIdx.x;
    int b = row / CAT_, i = row % CAT_;
    const float* src = (i == 0) ? (g_h2 + (size_t)b * 1025 * C_)
                                : (g_tok + ((size_t)b * W_ + (i - 1)) * C_);
    float* dst = g_cat + (size_t)row * C_;
    for (int c = threadIdx.x; c < C_; c += blockDim.x) dst[c] = src[c];
}

// ---------------------------------------------------------------------------
// Launch
// ---------------------------------------------------------------------------
extern "C" void kernel_launch(void* const* d_in, const int* in_sizes, int n_in,
                              void* d_out, int out_size) {
    const float* x      = (const float*)d_in[0];
    const float* n1w    = (const float*)d_in[1];
    const float* n1b    = (const float*)d_in[2];
    const float* qkv_w  = (const float*)d_in[3];
    const float* proj_w = (const float*)d_in[4];
    const float* proj_b = (const float*)d_in[5];
    const float* n2w    = (const float*)d_in[6];
    const float* n2b    = (const float*)d_in[7];
    const float* pool_w = (const float*)d_in[8];
    const float* pool_b = (const float*)d_in[9];
    const float* n3w    = (const float*)d_in[10];
    const float* n3b    = (const float*)d_in[11];
    const float* fc1_w  = (const float*)d_in[12];
    const float* fc1_b  = (const float*)d_in[13];
    const float* fc2_w  = (const float*)d_in[14];
    const float* fc2_b  = (const float*)d_in[15];
    float* out = (float*)d_out;

    float *h1, *qkvp, *att, *res, *h2, *tok, *cat, *h3, *fc1o;
    cudaGetSymbolAddress((void**)&h1,   g_h1);
    cudaGetSymbolAddress((void**)&qkvp, g_qkv);
    cudaGetSymbolAddress((void**)&att,  g_att);
    cudaGetSymbolAddress((void**)&res,  g_res);
    cudaGetSymbolAddress((void**)&h2,   g_h2);
    cudaGetSymbolAddress((void**)&tok,  g_tok);
    cudaGetSymbolAddress((void**)&cat,  g_cat);
    cudaGetSymbolAddress((void**)&h3,   g_h3);
    cudaGetSymbolAddress((void**)&fc1o, g_fc1);

    static int smemSet = 0;
    if (!smemSet) {
        cudaFuncSetAttribute(tgemm_kernel,
                             cudaFuncAttributeMaxDynamicSharedMemorySize, TG_SMEM);
        smemSet = 1;
    }

    const int MROWS = B_ * M_;        // 8208
    const int PROWS = B_ * W_;        // 2048
    const int CROWS = B_ * CAT_;      // 2056

    key_precompute_kernel<<<1, 1024>>>();
    ln_kernel<<<dim3(1025, B_), 128>>>(x, h1, n1w, n1b, 1025, M_);
    zero_pad_kernel<<<B_, C_>>>();

    tgemm_kernel<<<dim3(1152 / 64, (MROWS + 127) / 128), 256, TG_SMEM>>>(
        MROWS, 3 * C_, C_, h1, qkv_w, nullptr, nullptr, qkvp, 0, 0);

    attn_token_kernel<<<(B_ * H_ * NT_) / 8, 256>>>();
    attn_cls_part_kernel<<<dim3(8, B_ * H_), 128>>>();
    attn_cls_comb_kernel<<<B_ * H_, 64>>>();
    attn_pad_kernel<<<dim3(12, B_), 256>>>();

    tgemm_kernel<<<dim3(C_ / 64, (MROWS + 127) / 128), 256, TG_SMEM>>>(
        MROWS, C_, C_, att, proj_w, proj_b, h1, res, 0, 0);

    ln_kernel<<<dim3(1025, B_), 128>>>(res, h2, n2w, n2b, M_, 1025);

    // pool GEMM with fused window gather (A = g_h2)
    tgemm_kernel<<<dim3(C_ / 64, PROWS / 128), 256, TG_SMEM>>>(
        PROWS, C_, 9 * C_, h2, pool_w, pool_b, nullptr, tok, 0, 1);

    concat_kernel<<<B_ * CAT_, 128>>>();
    ln_kernel<<<dim3(CAT_, B_), 128>>>(cat, h3, n3w, n3b, CAT_, CAT_);

    tgemm_kernel<<<dim3(HID_ / 64, (CROWS + 127) / 128), 256, TG_SMEM>>>(
        CROWS, HID_, C_, h3, fc1_w, fc1_b, nullptr, fc1o, 1, 0);
    tgemm_kernel<<<dim3(C_ / 64, (CROWS + 127) / 128), 256, TG_SMEM>>>(
        CROWS, C_, HID_, fc1o, fc2_w, fc2_b, nullptr, out, 0, 0);
}

// round 12
// speedup vs baseline: 1.0684x; 1.0684x over previous
#include <cuda_runtime.h>
#include <math.h>

#define B_    8
#define M_    1026
#define NT_   1024
#define C_    384
#define H_    6
#define D_    64
#define HID_  1536
#define W_    256
#define CAT_  257
#define SCALE_ 0.4082482904638631f

// ---------------------------------------------------------------------------
// Scratch
// ---------------------------------------------------------------------------
__device__ float g_h1  [B_*M_*C_];
__device__ float g_qkv [B_*M_*3*C_];
__device__ float g_att [B_*M_*C_];
__device__ float g_res [B_*M_*C_];
__device__ float g_h2  [B_*(NT_+1)*C_];
__device__ float g_tok [B_*W_*C_];
__device__ float g_cat [B_*CAT_*C_];
__device__ float g_h3  [B_*CAT_*C_];
__device__ float g_fc1 [B_*CAT_*HID_];
__device__ float g_clsp[48*8*66];        // CLS split-K partials: m, s, o[64]
// precomputed sparse-attention key table
__device__ int   g_keys[NT_*32];         // float-offset (key*1152); 0 = CLS/filler
__device__ int   g_kcnt[NT_];

// ---------------------------------------------------------------------------
// Helpers
// ---------------------------------------------------------------------------
__device__ __forceinline__ float warpSum(float v) {
#pragma unroll
    for (int o = 16; o > 0; o >>= 1) v += __shfl_xor_sync(0xffffffffu, v, o);
    return v;
}
__device__ __forceinline__ float warpMax(float v) {
#pragma unroll
    for (int o = 16; o > 0; o >>= 1) v = fmaxf(v, __shfl_xor_sync(0xffffffffu, v, o));
    return v;
}
__device__ __forceinline__ unsigned f2tf(float f) {
    unsigned u;
    asm("cvt.rna.tf32.f32 %0, %1;" : "=r"(u) : "f"(f));
    return u;
}
__device__ __forceinline__ void cpasync16(void* smem_dst, const void* gsrc, bool pred) {
    unsigned saddr = (unsigned)__cvta_generic_to_shared(smem_dst);
    int sz = pred ? 16 : 0;
    asm volatile("cp.async.ca.shared.global [%0], [%1], 16, %2;\n"
                 :: "r"(saddr), "l"(gsrc), "r"(sz));
}

// ---------------------------------------------------------------------------
// Key table precompute: one block, 1024 threads (runs once per launch, ~2us)
// ---------------------------------------------------------------------------
__global__ void key_precompute_kernel() {
    int t = threadIdx.x;    // 0..1023
    int r = t >> 5, c = t & 31;
    int rl[5], cl[5];
    int nr = 0, nc = 0;
#pragma unroll
    for (int dr = -2; dr <= 2; ++dr) {
        int rp = r + dr;
        if (rp < 0 || rp > 31) continue;
        int lo = (r > rp ? r : rp) - 1; if (lo < 0) lo = 0;
        int hi = (r < rp ? r : rp) + 1; if (hi > 30) hi = 30;
        int fe = lo + (lo & 1);
        if (fe <= hi) rl[nr++] = rp;
    }
#pragma unroll
    for (int dc = -2; dc <= 2; ++dc) {
        int cp = c + dc;
        if (cp < 0 || cp > 31) continue;
        int lo = (c > cp ? c : cp) - 1; if (lo < 0) lo = 0;
        int hi = (c < cp ? c : cp) + 1; if (hi > 30) hi = 30;
        int fe = lo + (lo & 1);
        if (fe <= hi) cl[nc++] = cp;
    }
    int cnt = 1 + nr * nc;
    g_kcnt[t] = cnt;
    for (int j = 0; j < 32; ++j) {
        int key = 0;   // CLS row (also filler for invalid lanes)
        if (j >= 1 && j < cnt) {
            int i = j - 1;
            key = rl[i / nc] * 32 + cl[i % nc] + 1;
        }
        g_keys[t * 32 + j] = key * (3 * C_);   // float offset within batch
    }
}

// ---------------------------------------------------------------------------
// LayerNorm (round-3 exact)
// ---------------------------------------------------------------------------
__global__ void ln_kernel(const float* __restrict__ in, float* __restrict__ out,
                          const float* __restrict__ gw, const float* __restrict__ gb,
                          int inStride, int outStride) {
    int i = blockIdx.x, b = blockIdx.y;
    const float* xr = in + ((size_t)b * inStride + i) * C_;
    float* yr = out + ((size_t)b * outStride + i) * C_;
    int tid = threadIdx.x;
    float v0 = xr[tid], v1 = xr[tid + 128], v2 = xr[tid + 256];
    __shared__ float sm[4];
    float s = warpSum(v0 + v1 + v2);
    if ((tid & 31) == 0) sm[tid >> 5] = s;
    __syncthreads();
    float mu = (sm[0] + sm[1] + sm[2] + sm[3]) * (1.f / 384.f);
    float d0 = v0 - mu, d1 = v1 - mu, d2 = v2 - mu;
    __syncthreads();
    float q = warpSum(d0 * d0 + d1 * d1 + d2 * d2);
    if ((tid & 31) == 0) sm[tid >> 5] = q;
    __syncthreads();
    float var = (sm[0] + sm[1] + sm[2] + sm[3]) * (1.f / 384.f);
    float rs = rsqrtf(var + 1e-5f);
    yr[tid]       = d0 * rs * gw[tid]       + gb[tid];
    yr[tid + 128] = d1 * rs * gw[tid + 128] + gb[tid + 128];
    yr[tid + 256] = d2 * rs * gw[tid + 256] + gb[tid + 256];
}

__global__ void zero_pad_kernel() {
    g_h1[((size_t)blockIdx.x * M_ + 1025) * C_ + threadIdx.x] = 0.f;
}

// ---------------------------------------------------------------------------
// TF32 tensor-core GEMM (round-3/8 proven config): 128x64x32, 256 threads,
// 2-stage cp.async, warp tile 32x32 via m16n8k8. Natural register allocation
// (80 regs / 3 CTAs measured fastest; forcing 64 spilled and regressed).
// GATHER template: index math for the pool-gather A-path compiled ONLY into
// the pool instantiation, keeping the 4 hot launches lean.
// ---------------------------------------------------------------------------
#define KP_ 36
#define TG_SMEM ((2*128*KP_ + 2*64*KP_) * 4)   // 55296 bytes

template<int GATHER>
__global__ void __launch_bounds__(256)
tgemm_kernel(int M, int N, int K,
             const float* __restrict__ A, const float* __restrict__ Wt,
             const float* __restrict__ bias, const float* __restrict__ resid,
             float* __restrict__ Cc, int doGelu) {
    extern __shared__ float dyn[];
    float (*sA)[128][KP_] = (float(*)[128][KP_])dyn;
    float (*sB)[64][KP_]  = (float(*)[64][KP_])(dyn + 2 * 128 * KP_);

    int tid  = threadIdx.x;
    int lane = tid & 31;
    int wid  = tid >> 5;
    int wm   = wid & 3;
    int wn   = wid >> 2;
    int lr   = lane >> 2;
    int lc   = lane & 3;

    int bm = blockIdx.y * 128;
    int bn = blockIdx.x * 64;

    int ldRow = tid >> 3;   // 0..31
    int ldC4  = tid & 7;    // 0..7

    float acc[2][4][4];
#pragma unroll
    for (int mt = 0; mt < 2; ++mt)
#pragma unroll
        for (int nt = 0; nt < 4; ++nt)
#pragma unroll
            for (int e = 0; e < 4; ++e) acc[mt][nt][e] = 0.f;

    int nIter = K >> 5;

    auto loadTile = [&](int it, int s) {
        int k0 = it << 5;
        if (!GATHER) {
#pragma unroll
            for (int i = 0; i < 4; ++i) {
                int r = ldRow + i * 32;
                int gr = bm + r;
                bool p = gr < M;
                const float* src = A + (size_t)(p ? gr : 0) * K + k0 + ldC4 * 4;
                cpasync16(&sA[s][r][ldC4 * 4], src, p);
            }
        } else {
            int kk = k0 / 384;
            int c0 = k0 - kk * 384;
#pragma unroll
            for (int i = 0; i < 4; ++i) {
                int r = ldRow + i * 32;
                int gr = bm + r;
                int b = gr >> 8, w = gr & 255;
                int wi = w >> 4, wj = w & 15;
                int rr = 2 * wi + kk / 3 - 1;
                int cc = 2 * wj + kk % 3 - 1;
                int hrow = (rr < 0 || cc < 0) ? 1024 : rr * 32 + cc + 1;
                const float* src = A + ((size_t)b * 1025 + hrow) * 384 + c0 + ldC4 * 4;
                cpasync16(&sA[s][r][ldC4 * 4], src, true);
            }
        }
#pragma unroll
        for (int i = 0; i < 2; ++i) {
            int n = ldRow + i * 32;
            int gn = bn + n;
            bool p = gn < N;
            const float* src = Wt + (size_t)(p ? gn : 0) * K + k0 + ldC4 * 4;
            cpasync16(&sB[s][n][ldC4 * 4], src, p);
        }
    };

    loadTile(0, 0);
    asm volatile("cp.async.commit_group;\n");

    for (int it = 0; it < nIter; ++it) {
        int s = it & 1;
        if (it + 1 < nIter) {
            loadTile(it + 1, s ^ 1);
            asm volatile("cp.async.commit_group;\n");
            asm volatile("cp.async.wait_group 1;\n");
        } else {
            asm volatile("cp.async.wait_group 0;\n");
        }
        __syncthreads();

#pragma unroll
        for (int ks = 0; ks < 4; ++ks) {
            int kk = ks * 8;
            unsigned a[2][4], bf[4][2];
#pragma unroll
            for (int mt = 0; mt < 2; ++mt) {
                int row = wm * 32 + mt * 16 + lr;
                a[mt][0] = f2tf(sA[s][row    ][kk + lc]);
                a[mt][1] = f2tf(sA[s][row + 8][kk + lc]);
                a[mt][2] = f2tf(sA[s][row    ][kk + lc + 4]);
                a[mt][3] = f2tf(sA[s][row + 8][kk + lc + 4]);
            }
#pragma unroll
            for (int nt = 0; nt < 4; ++nt) {
                int n = wn * 32 + nt * 8 + lr;
                bf[nt][0] = f2tf(sB[s][n][kk + lc]);
                bf[nt][1] = f2tf(sB[s][n][kk + lc + 4]);
            }
#pragma unroll
            for (int mt = 0; mt < 2; ++mt)
#pragma unroll
                for (int nt = 0; nt < 4; ++nt) {
                    asm volatile(
                        "mma.sync.aligned.m16n8k8.row.col.f32.tf32.tf32.f32 "
                        "{%0,%1,%2,%3}, {%4,%5,%6,%7}, {%8,%9}, {%0,%1,%2,%3};\n"
                        : "+f"(acc[mt][nt][0]), "+f"(acc[mt][nt][1]),
                          "+f"(acc[mt][nt][2]), "+f"(acc[mt][nt][3])
                        : "r"(a[mt][0]), "r"(a[mt][1]), "r"(a[mt][2]), "r"(a[mt][3]),
                          "r"(bf[nt][0]), "r"(bf[nt][1]));
                }
        }
        __syncthreads();
    }

#pragma unroll
    for (int mt = 0; mt < 2; ++mt) {
#pragma unroll
        for (int nt = 0; nt < 4; ++nt) {
            int col = bn + wn * 32 + nt * 8 + 2 * lc;
            float bx = 0.f, by = 0.f;
            if (bias) { bx = bias[col]; by = bias[col + 1]; }
#pragma unroll
            for (int half = 0; half < 2; ++half) {
                int row = bm + wm * 32 + mt * 16 + lr + half * 8;
                if (row >= M) continue;
                float vx = acc[mt][nt][2 * half + 0] + bx;
                float vy = acc[mt][nt][2 * half + 1] + by;
                if (resid) {
                    const float2 rv = *(const float2*)(resid + (size_t)row * N + col);
                    vx += rv.x; vy += rv.y;
                }
                if (doGelu) {
                    vx = 0.5f * vx * (1.f + erff(vx * 0.70710678118654752f));
                    vy = 0.5f * vy * (1.f + erff(vy * 0.70710678118654752f));
                }
                *(float2*)(Cc + (size_t)row * N + col) = make_float2(vx, vy);
            }
        }
    }
}

// ---------------------------------------------------------------------------
// Sparse attention (token queries): one warp per (b,h,t), split-warp QK,
// precomputed key table (float offsets).
// ---------------------------------------------------------------------------
__global__ void attn_token_kernel() {
    int gw = (blockIdx.x * blockDim.x + threadIdx.x) >> 5;
    int lane = threadIdx.x & 31;
    int t  = gw & 1023;
    int bh = gw >> 10;
    int h = bh % H_;
    int b = bh / H_;

    int key_off = g_keys[t * 32 + lane];
    int cnt     = g_kcnt[t];

    const float* qp = g_qkv + ((size_t)b * M_ + (t + 1)) * (3 * C_) + h * D_;
    int hl = lane & 15;
    float4 qv = *(const float4*)(qp + hl * 4);
    const float* kbase = g_qkv + (size_t)b * M_ * (3 * C_) + C_ + h * D_;

    float s = -INFINITY;
    for (int j0 = 0; j0 < 26; j0 += 2) {
        if (j0 >= cnt) break;
        int ka = __shfl_sync(0xffffffffu, key_off, j0);
        int kb = __shfl_sync(0xffffffffu, key_off, j0 + 1);
        int kidx = (lane < 16) ? ka : kb;
        float4 kv = *(const float4*)(kbase + kidx + hl * 4);
        float d = qv.x * kv.x + qv.y * kv.y + qv.z * kv.z + qv.w * kv.w;
        d += __shfl_xor_sync(0xffffffffu, d, 8);
        d += __shfl_xor_sync(0xffffffffu, d, 4);
        d += __shfl_xor_sync(0xffffffffu, d, 2);
        d += __shfl_xor_sync(0xffffffffu, d, 1);
        float dx = __shfl_xor_sync(0xffffffffu, d, 16);
        float da = (lane < 16) ? d : dx;
        float db = (lane < 16) ? dx : d;
        if (lane == j0)     s = da * SCALE_;
        if (lane == j0 + 1) s = db * SCALE_;
    }
    if (lane >= cnt) s = -INFINITY;

    float m = fmaxf(warpMax(s), 0.f);
    float p = (lane < cnt) ? expf(s - m) : 0.f;
    float denom = warpSum(p) + expf(-m);
    float inv = 1.f / denom;

    const float* vbase = g_qkv + (size_t)b * M_ * (3 * C_) + 2 * C_ + h * D_;
    float o0 = 0.f, o1 = 0.f;
    for (int j = 0; j < cnt; ++j) {
        float pj = __shfl_sync(0xffffffffu, p, j);
        int   kj = __shfl_sync(0xffffffffu, key_off, j);
        float2 vv = *(const float2*)(vbase + kj + 2 * lane);
        o0 += pj * vv.x;
        o1 += pj * vv.y;
    }
    float* op = g_att + ((size_t)b * M_ + (t + 1)) * C_ + h * D_;
    *(float2*)(op + 2 * lane) = make_float2(o0 * inv, o1 * inv);
}

// ---------------------------------------------------------------------------
// CLS attention, split-K.
// ---------------------------------------------------------------------------
__global__ void attn_cls_part_kernel() {
    int chunk = blockIdx.x;          // 0..7
    int bh    = blockIdx.y;          // 0..47
    int b = bh / H_, h = bh % H_;
    int start = chunk * 129;
    int end   = start + 129; if (end > 1025) end = 1025;
    int cnt   = end - start;
    int tid = threadIdx.x;           // 128

    __shared__ float sq[64];
    __shared__ float sc[132];
    __shared__ float sred[4];
    __shared__ float oacc[128];

    const float* qp = g_qkv + (size_t)(b * M_) * (3 * C_) + h * D_;
    if (tid < 64) sq[tid] = qp[tid];
    __syncthreads();

    for (int j = tid; j < cnt; j += 128) {
        const float* kp = g_qkv + ((size_t)b * M_ + start + j) * (3 * C_) + C_ + h * D_;
        float acc = 0.f;
#pragma unroll
        for (int d0 = 0; d0 < D_; d0 += 4) {
            float4 kv = *(const float4*)(kp + d0);
            acc += sq[d0] * kv.x + sq[d0 + 1] * kv.y + sq[d0 + 2] * kv.z + sq[d0 + 3] * kv.w;
        }
        sc[j] = acc * SCALE_;
    }
    __syncthreads();

    float m = -INFINITY;
    for (int j = tid; j < cnt; j += 128) m = fmaxf(m, sc[j]);
    m = warpMax(m);
    if ((tid & 31) == 0) sred[tid >> 5] = m;
    __syncthreads();
    m = fmaxf(fmaxf(sred[0], sred[1]), fmaxf(sred[2], sred[3]));
    __syncthreads();

    float ls = 0.f;
    for (int j = tid; j < cnt; j += 128) {
        float pv = expf(sc[j] - m);
        sc[j] = pv;
        ls += pv;
    }
    ls = warpSum(ls);
    if ((tid & 31) == 0) sred[tid >> 5] = ls;
    __syncthreads();
    float ssum = sred[0] + sred[1] + sred[2] + sred[3];

    int d = tid & 63, grp = tid >> 6;
    float acc = 0.f;
    for (int j = grp; j < cnt; j += 2)
        acc += sc[j] * g_qkv[((size_t)b * M_ + start + j) * (3 * C_) + 2 * C_ + h * D_ + d];
    oacc[tid] = acc;
    __syncthreads();

    float* dst = g_clsp + ((size_t)bh * 8 + chunk) * 66;
    if (tid < 64) dst[2 + tid] = oacc[tid] + oacc[tid + 64];
    if (tid == 0) { dst[0] = m; dst[1] = ssum; }
}

__global__ void attn_cls_comb_kernel() {
    int bh = blockIdx.x;             // 0..47
    int b = bh / H_, h = bh % H_;
    int d = threadIdx.x;             // 64
    const float* src = g_clsp + (size_t)bh * 8 * 66;
    float M = 0.f;
#pragma unroll
    for (int c = 0; c < 8; ++c) M = fmaxf(M, src[c * 66]);
    float denom = expf(-M);
    float o = 0.f;
#pragma unroll
    for (int c = 0; c < 8; ++c) {
        float w = expf(src[c * 66] - M);
        denom += src[c * 66 + 1] * w;
        o += src[c * 66 + 2 + d] * w;
    }
    g_att[(size_t)(b * M_) * C_ + h * D_ + d] = o / denom;
}

// Pad query: parallel over rows. grid (12, B), block 256.
__global__ void attn_pad_kernel() {
    int b = blockIdx.y;
    int cg = blockIdx.x;
    int tid = threadIdx.x;
    int cl = tid & 31;
    int rg = tid >> 5;
    int ch = cg * 32 + cl;
    const float* base = g_qkv + (size_t)b * M_ * (3 * C_) + 2 * C_ + ch;
    float acc = 0.f;
    for (int mrow = rg; mrow < 1025; mrow += 8)
        acc += base[(size_t)mrow * (3 * C_)];
    __shared__ float sm2[8][32];
    sm2[rg][cl] = acc;
    __syncthreads();
    if (tid < 32) {
        float a = 0.f;
#pragma unroll
        for (int rr = 0; rr < 8; ++rr) a += sm2[rr][tid];
        g_att[((size_t)b * M_ + 1025) * C_ + cg * 32 + tid] = a * (1.0f / 1026.0f);
    }
}

__global__ void concat_kernel() {
    int row = blockIdx.x;
    int b = row / CAT_, i = row % CAT_;
    const float* src = (i == 0) ? (g_h2 + (size_t)b * 1025 * C_)
                                : (g_tok + ((size_t)b * W_ + (i - 1)) * C_);
    float* dst = g_cat + (size_t)row * C_;
    for (int c = threadIdx.x; c < C_; c += blockDim.x) dst[c] = src[c];
}

// ---------------------------------------------------------------------------
// Launch
// ---------------------------------------------------------------------------
extern "C" void kernel_launch(void* const* d_in, const int* in_sizes, int n_in,
                              void* d_out, int out_size) {
    const float* x      = (const float*)d_in[0];
    const float* n1w    = (const float*)d_in[1];
    const float* n1b    = (const float*)d_in[2];
    const float* qkv_w  = (const float*)d_in[3];
    const float* proj_w = (const float*)d_in[4];
    const float* proj_b = (const float*)d_in[5];
    const float* n2w    = (const float*)d_in[6];
    const float* n2b    = (const float*)d_in[7];
    const float* pool_w = (const float*)d_in[8];
    const float* pool_b = (const float*)d_in[9];
    const float* n3w    = (const float*)d_in[10];
    const float* n3b    = (const float*)d_in[11];
    const float* fc1_w  = (const float*)d_in[12];
    const float* fc1_b  = (const float*)d_in[13];
    const float* fc2_w  = (const float*)d_in[14];
    const float* fc2_b  = (const float*)d_in[15];
    float* out = (float*)d_out;

    float *h1, *qkvp, *att, *res, *h2, *tok, *cat, *h3, *fc1o;
    cudaGetSymbolAddress((void**)&h1,   g_h1);
    cudaGetSymbolAddress((void**)&qkvp, g_qkv);
    cudaGetSymbolAddress((void**)&att,  g_att);
    cudaGetSymbolAddress((void**)&res,  g_res);
    cudaGetSymbolAddress((void**)&h2,   g_h2);
    cudaGetSymbolAddress((void**)&tok,  g_tok);
    cudaGetSymbolAddress((void**)&cat,  g_cat);
    cudaGetSymbolAddress((void**)&h3,   g_h3);
    cudaGetSymbolAddress((void**)&fc1o, g_fc1);

    static int smemSet = 0;
    if (!smemSet) {
        cudaFuncSetAttribute(tgemm_kernel<0>,
                             cudaFuncAttributeMaxDynamicSharedMemorySize, TG_SMEM);
        cudaFuncSetAttribute(tgemm_kernel<1>,
                             cudaFuncAttributeMaxDynamicSharedMemorySize, TG_SMEM);
        smemSet = 1;
    }

    const int MROWS = B_ * M_;        // 8208
    const int PROWS = B_ * W_;        // 2048
    const int CROWS = B_ * CAT_;      // 2056

    key_precompute_kernel<<<1, 1024>>>();
    ln_kernel<<<dim3(1025, B_), 128>>>(x, h1, n1w, n1b, 1025, M_);
    zero_pad_kernel<<<B_, C_>>>();

    tgemm_kernel<0><<<dim3(1152 / 64, (MROWS + 127) / 128), 256, TG_SMEM>>>(
        MROWS, 3 * C_, C_, h1, qkv_w, nullptr, nullptr, qkvp, 0);

    attn_token_kernel<<<(B_ * H_ * NT_) / 8, 256>>>();
    attn_cls_part_kernel<<<dim3(8, B_ * H_), 128>>>();
    attn_cls_comb_kernel<<<B_ * H_, 64>>>();
    attn_pad_kernel<<<dim3(12, B_), 256>>>();

    tgemm_kernel<0><<<dim3(C_ / 64, (MROWS + 127) / 128), 256, TG_SMEM>>>(
        MROWS, C_, C_, att, proj_w, proj_b, h1, res, 0);

    ln_kernel<<<dim3(1025, B_), 128>>>(res, h2, n2w, n2b, M_, 1025);

    // pool GEMM with fused window gather (A = g_h2)
    tgemm_kernel<1><<<dim3(C_ / 64, PROWS / 128), 256, TG_SMEM>>>(
        PROWS, C_, 9 * C_, h2, pool_w, pool_b, nullptr, tok, 0);

    concat_kernel<<<B_ * CAT_, 128>>>();
    ln_kernel<<<dim3(CAT_, B_), 128>>>(cat, h3, n3w, n3b, CAT_, CAT_);

    tgemm_kernel<0><<<dim3(HID_ / 64, (CROWS + 127) / 128), 256, TG_SMEM>>>(
        CROWS, HID_, C_, h3, fc1_w, fc1_b, nullptr, fc1o, 1);
    tgemm_kernel<0><<<dim3(C_ / 64, (CROWS + 127) / 128), 256, TG_SMEM>>>(
        CROWS, C_, HID_, fc1o, fc2_w, fc2_b, nullptr, out, 0);
}

// round 13
// speedup vs baseline: 1.1200x; 1.0483x over previous
#include <cuda_runtime.h>
#include <math.h>

#define B_    8
#define M_    1026
#define NT_   1024
#define C_    384
#define H_    6
#define D_    64
#define HID_  1536
#define W_    256
#define CAT_  257
#define SCALE_ 0.4082482904638631f

// ---------------------------------------------------------------------------
// Scratch
// ---------------------------------------------------------------------------
__device__ float g_h1  [B_*M_*C_];
__device__ float g_qkv [B_*M_*3*C_];
__device__ float g_att [B_*M_*C_];
__device__ float g_res [B_*M_*C_];
__device__ float g_h2  [B_*(NT_+1)*C_];
__device__ float g_tok [B_*W_*C_];
__device__ float g_cat [B_*CAT_*C_];
__device__ float g_h3  [B_*CAT_*C_];
__device__ float g_fc1 [B_*CAT_*HID_];
__device__ float g_clsp[48*8*66];        // CLS split-K partials: m, s, o[64]
// precomputed sparse-attention key table
__device__ int   g_keys[NT_*32];         // float-offset (key*1152); 0 = CLS/filler
__device__ int   g_kcnt[NT_];

// ---------------------------------------------------------------------------
// Helpers
// ---------------------------------------------------------------------------
__device__ __forceinline__ float warpSum(float v) {
#pragma unroll
    for (int o = 16; o > 0; o >>= 1) v += __shfl_xor_sync(0xffffffffu, v, o);
    return v;
}
__device__ __forceinline__ float warpMax(float v) {
#pragma unroll
    for (int o = 16; o > 0; o >>= 1) v = fmaxf(v, __shfl_xor_sync(0xffffffffu, v, o));
    return v;
}
__device__ __forceinline__ unsigned f2tf(float f) {
    unsigned u;
    asm("cvt.rna.tf32.f32 %0, %1;" : "=r"(u) : "f"(f));
    return u;
}
__device__ __forceinline__ unsigned f2tfu(unsigned raw) {
    unsigned u;
    asm("cvt.rna.tf32.f32 %0, %1;" : "=r"(u) : "f"(__uint_as_float(raw)));
    return u;
}
__device__ __forceinline__ void cpasync16(void* smem_dst, const void* gsrc, bool pred) {
    unsigned saddr = (unsigned)__cvta_generic_to_shared(smem_dst);
    int sz = pred ? 16 : 0;
    asm volatile("cp.async.ca.shared.global [%0], [%1], 16, %2;\n"
                 :: "r"(saddr), "l"(gsrc), "r"(sz));
}
__device__ __forceinline__ void ldsm4(unsigned& r0, unsigned& r1, unsigned& r2, unsigned& r3,
                                      unsigned addr) {
    asm volatile("ldmatrix.sync.aligned.m8n8.x4.shared.b16 {%0,%1,%2,%3}, [%4];\n"
                 : "=r"(r0), "=r"(r1), "=r"(r2), "=r"(r3) : "r"(addr));
}

// ---------------------------------------------------------------------------
// Key table precompute: one block, 1024 threads (runs once per launch, ~2us)
// ---------------------------------------------------------------------------
__global__ void key_precompute_kernel() {
    int t = threadIdx.x;    // 0..1023
    int r = t >> 5, c = t & 31;
    int rl[5], cl[5];
    int nr = 0, nc = 0;
#pragma unroll
    for (int dr = -2; dr <= 2; ++dr) {
        int rp = r + dr;
        if (rp < 0 || rp > 31) continue;
        int lo = (r > rp ? r : rp) - 1; if (lo < 0) lo = 0;
        int hi = (r < rp ? r : rp) + 1; if (hi > 30) hi = 30;
        int fe = lo + (lo & 1);
        if (fe <= hi) rl[nr++] = rp;
    }
#pragma unroll
    for (int dc = -2; dc <= 2; ++dc) {
        int cp = c + dc;
        if (cp < 0 || cp > 31) continue;
        int lo = (c > cp ? c : cp) - 1; if (lo < 0) lo = 0;
        int hi = (c < cp ? c : cp) + 1; if (hi > 30) hi = 30;
        int fe = lo + (lo & 1);
        if (fe <= hi) cl[nc++] = cp;
    }
    int cnt = 1 + nr * nc;
    g_kcnt[t] = cnt;
    for (int j = 0; j < 32; ++j) {
        int key = 0;   // CLS row (also filler for invalid lanes)
        if (j >= 1 && j < cnt) {
            int i = j - 1;
            key = rl[i / nc] * 32 + cl[i % nc] + 1;
        }
        g_keys[t * 32 + j] = key * (3 * C_);   // float offset within batch
    }
}

// ---------------------------------------------------------------------------
// LayerNorm (round-3 exact)
// ---------------------------------------------------------------------------
__global__ void ln_kernel(const float* __restrict__ in, float* __restrict__ out,
                          const float* __restrict__ gw, const float* __restrict__ gb,
                          int inStride, int outStride) {
    int i = blockIdx.x, b = blockIdx.y;
    const float* xr = in + ((size_t)b * inStride + i) * C_;
    float* yr = out + ((size_t)b * outStride + i) * C_;
    int tid = threadIdx.x;
    float v0 = xr[tid], v1 = xr[tid + 128], v2 = xr[tid + 256];
    __shared__ float sm[4];
    float s = warpSum(v0 + v1 + v2);
    if ((tid & 31) == 0) sm[tid >> 5] = s;
    __syncthreads();
    float mu = (sm[0] + sm[1] + sm[2] + sm[3]) * (1.f / 384.f);
    float d0 = v0 - mu, d1 = v1 - mu, d2 = v2 - mu;
    __syncthreads();
    float q = warpSum(d0 * d0 + d1 * d1 + d2 * d2);
    if ((tid & 31) == 0) sm[tid >> 5] = q;
    __syncthreads();
    float var = (sm[0] + sm[1] + sm[2] + sm[3]) * (1.f / 384.f);
    float rs = rsqrtf(var + 1e-5f);
    yr[tid]       = d0 * rs * gw[tid]       + gb[tid];
    yr[tid + 128] = d1 * rs * gw[tid + 128] + gb[tid + 128];
    yr[tid + 256] = d2 * rs * gw[tid + 256] + gb[tid + 256];
}

__global__ void zero_pad_kernel() {
    g_h1[((size_t)blockIdx.x * M_ + 1025) * C_ + threadIdx.x] = 0.f;
}

// ---------------------------------------------------------------------------
// TF32 tensor-core GEMM: 128x64x32, 256 threads, 2-stage cp.async,
// warp tile 32x32 via m16n8k8, fragment loads via ldmatrix.x4
// (16 LDSM replace 96 scalar LDS per k-tile; KP_=36 keeps ldmatrix rows
// conflict-free: 8 rows at 36-word stride cover all 32 banks once).
// cvt to tf32 applied to ldmatrix outputs -> numerics identical.
// GATHER template: pool-gather A-path index math only in the pool instance.
// ---------------------------------------------------------------------------
#define KP_ 36
#define TG_SMEM ((2*128*KP_ + 2*64*KP_) * 4)   // 55296 bytes
#define SA_STAGE_BYTES (128*KP_*4)
#define SB_STAGE_BYTES (64*KP_*4)
#define SB_BASE_BYTES  (2*128*KP_*4)

template<int GATHER>
__global__ void __launch_bounds__(256)
tgemm_kernel(int M, int N, int K,
             const float* __restrict__ A, const float* __restrict__ Wt,
             const float* __restrict__ bias, const float* __restrict__ resid,
             float* __restrict__ Cc, int doGelu) {
    extern __shared__ float dyn[];
    float (*sA)[128][KP_] = (float(*)[128][KP_])dyn;
    float (*sB)[64][KP_]  = (float(*)[64][KP_])(dyn + 2 * 128 * KP_);

    int tid  = threadIdx.x;
    int lane = tid & 31;
    int wid  = tid >> 5;
    int wm   = wid & 3;
    int wn   = wid >> 2;
    int lr   = lane >> 2;
    int lc   = lane & 3;

    int bm = blockIdx.y * 128;
    int bn = blockIdx.x * 64;

    int ldRow = tid >> 3;   // 0..31
    int ldC4  = tid & 7;    // 0..7

    // ldmatrix per-lane base addresses (stage 0, kk = 0)
    unsigned smemU = (unsigned)__cvta_generic_to_shared(dyn);
    int lm = lane >> 3;       // matrix index 0..3
    int lrr = lane & 7;       // row within matrix
    // A matrices for mt: {rows base+(lm&1)*8+lrr, cols (lm>>1)*4}
    unsigned aAddr[2];
#pragma unroll
    for (int mt = 0; mt < 2; ++mt)
        aAddr[mt] = smemU +
            ((unsigned)((wm * 32 + mt * 16 + (lm & 1) * 8 + lrr) * KP_ + (lm >> 1) * 4)) * 4u;
    // B matrices: matrix lm -> rows wn*32 + lm*8 + lrr, col half added at use
    unsigned bAddr = smemU + SB_BASE_BYTES +
        ((unsigned)((wn * 32 + lm * 8 + lrr) * KP_)) * 4u;

    float acc[2][4][4];
#pragma unroll
    for (int mt = 0; mt < 2; ++mt)
#pragma unroll
        for (int nt = 0; nt < 4; ++nt)
#pragma unroll
            for (int e = 0; e < 4; ++e) acc[mt][nt][e] = 0.f;

    int nIter = K >> 5;

    auto loadTile = [&](int it, int s) {
        int k0 = it << 5;
        if (!GATHER) {
#pragma unroll
            for (int i = 0; i < 4; ++i) {
                int r = ldRow + i * 32;
                int gr = bm + r;
                bool p = gr < M;
                const float* src = A + (size_t)(p ? gr : 0) * K + k0 + ldC4 * 4;
                cpasync16(&sA[s][r][ldC4 * 4], src, p);
            }
        } else {
            int kk = k0 / 384;
            int c0 = k0 - kk * 384;
#pragma unroll
            for (int i = 0; i < 4; ++i) {
                int r = ldRow + i * 32;
                int gr = bm + r;
                int b = gr >> 8, w = gr & 255;
                int wi = w >> 4, wj = w & 15;
                int rr = 2 * wi + kk / 3 - 1;
                int cc = 2 * wj + kk % 3 - 1;
                int hrow = (rr < 0 || cc < 0) ? 1024 : rr * 32 + cc + 1;
                const float* src = A + ((size_t)b * 1025 + hrow) * 384 + c0 + ldC4 * 4;
                cpasync16(&sA[s][r][ldC4 * 4], src, true);
            }
        }
#pragma unroll
        for (int i = 0; i < 2; ++i) {
            int n = ldRow + i * 32;
            int gn = bn + n;
            bool p = gn < N;
            const float* src = Wt + (size_t)(p ? gn : 0) * K + k0 + ldC4 * 4;
            cpasync16(&sB[s][n][ldC4 * 4], src, p);
        }
    };

    loadTile(0, 0);
    asm volatile("cp.async.commit_group;\n");

    for (int it = 0; it < nIter; ++it) {
        int s = it & 1;
        if (it + 1 < nIter) {
            loadTile(it + 1, s ^ 1);
            asm volatile("cp.async.commit_group;\n");
            asm volatile("cp.async.wait_group 1;\n");
        } else {
            asm volatile("cp.async.wait_group 0;\n");
        }
        __syncthreads();

        unsigned sAoff = (unsigned)(s * SA_STAGE_BYTES);
        unsigned sBoff = (unsigned)(s * SB_STAGE_BYTES);

#pragma unroll
        for (int ks = 0; ks < 4; ++ks) {
            unsigned kOff = (unsigned)(ks * 8 * 4);   // kk*4 bytes
            unsigned a[2][4], bf[4][2];
            // A fragments: one ldmatrix.x4 per mt
#pragma unroll
            for (int mt = 0; mt < 2; ++mt)
                ldsm4(a[mt][0], a[mt][1], a[mt][2], a[mt][3],
                      aAddr[mt] + sAoff + kOff);
            // B fragments: two ldmatrix.x4 (col halves kk, kk+4)
            {
                unsigned b0, b1, b2, b3;
                ldsm4(b0, b1, b2, b3, bAddr + sBoff + kOff);
                bf[0][0] = b0; bf[1][0] = b1; bf[2][0] = b2; bf[3][0] = b3;
                ldsm4(b0, b1, b2, b3, bAddr + sBoff + kOff + 16);
                bf[0][1] = b0; bf[1][1] = b1; bf[2][1] = b2; bf[3][1] = b3;
            }
            // cvt to tf32 (numerics identical to previous rounds)
#pragma unroll
            for (int mt = 0; mt < 2; ++mt)
#pragma unroll
                for (int e = 0; e < 4; ++e) a[mt][e] = f2tfu(a[mt][e]);
#pragma unroll
            for (int nt = 0; nt < 4; ++nt) {
                bf[nt][0] = f2tfu(bf[nt][0]);
                bf[nt][1] = f2tfu(bf[nt][1]);
            }
#pragma unroll
            for (int mt = 0; mt < 2; ++mt)
#pragma unroll
                for (int nt = 0; nt < 4; ++nt) {
                    asm volatile(
                        "mma.sync.aligned.m16n8k8.row.col.f32.tf32.tf32.f32 "
                        "{%0,%1,%2,%3}, {%4,%5,%6,%7}, {%8,%9}, {%0,%1,%2,%3};\n"
                        : "+f"(acc[mt][nt][0]), "+f"(acc[mt][nt][1]),
                          "+f"(acc[mt][nt][2]), "+f"(acc[mt][nt][3])
                        : "r"(a[mt][0]), "r"(a[mt][1]), "r"(a[mt][2]), "r"(a[mt][3]),
                          "r"(bf[nt][0]), "r"(bf[nt][1]));
                }
        }
        __syncthreads();
    }

#pragma unroll
    for (int mt = 0; mt < 2; ++mt) {
#pragma unroll
        for (int nt = 0; nt < 4; ++nt) {
            int col = bn + wn * 32 + nt * 8 + 2 * lc;
            float bx = 0.f, by = 0.f;
            if (bias) { bx = bias[col]; by = bias[col + 1]; }
#pragma unroll
            for (int half = 0; half < 2; ++half) {
                int row = bm + wm * 32 + mt * 16 + lr + half * 8;
                if (row >= M) continue;
                float vx = acc[mt][nt][2 * half + 0] + bx;
                float vy = acc[mt][nt][2 * half + 1] + by;
                if (resid) {
                    const float2 rv = *(const float2*)(resid + (size_t)row * N + col);
                    vx += rv.x; vy += rv.y;
                }
                if (doGelu) {
                    vx = 0.5f * vx * (1.f + erff(vx * 0.70710678118654752f));
                    vy = 0.5f * vy * (1.f + erff(vy * 0.70710678118654752f));
                }
                *(float2*)(Cc + (size_t)row * N + col) = make_float2(vx, vy);
            }
        }
    }
}

// ---------------------------------------------------------------------------
// Sparse attention (token queries): one warp per (b,h,t), split-warp QK,
// precomputed key table (float offsets).
// ---------------------------------------------------------------------------
__global__ void attn_token_kernel() {
    int gw = (blockIdx.x * blockDim.x + threadIdx.x) >> 5;
    int lane = threadIdx.x & 31;
    int t  = gw & 1023;
    int bh = gw >> 10;
    int h = bh % H_;
    int b = bh / H_;

    int key_off = g_keys[t * 32 + lane];
    int cnt     = g_kcnt[t];

    const float* qp = g_qkv + ((size_t)b * M_ + (t + 1)) * (3 * C_) + h * D_;
    int hl = lane & 15;
    float4 qv = *(const float4*)(qp + hl * 4);
    const float* kbase = g_qkv + (size_t)b * M_ * (3 * C_) + C_ + h * D_;

    float s = -INFINITY;
    for (int j0 = 0; j0 < 26; j0 += 2) {
        if (j0 >= cnt) break;
        int ka = __shfl_sync(0xffffffffu, key_off, j0);
        int kb = __shfl_sync(0xffffffffu, key_off, j0 + 1);
        int kidx = (lane < 16) ? ka : kb;
        float4 kv = *(const float4*)(kbase + kidx + hl * 4);
        float d = qv.x * kv.x + qv.y * kv.y + qv.z * kv.z + qv.w * kv.w;
        d += __shfl_xor_sync(0xffffffffu, d, 8);
        d += __shfl_xor_sync(0xffffffffu, d, 4);
        d += __shfl_xor_sync(0xffffffffu, d, 2);
        d += __shfl_xor_sync(0xffffffffu, d, 1);
        float dx = __shfl_xor_sync(0xffffffffu, d, 16);
        float da = (lane < 16) ? d : dx;
        float db = (lane < 16) ? dx : d;
        if (lane == j0)     s = da * SCALE_;
        if (lane == j0 + 1) s = db * SCALE_;
    }
    if (lane >= cnt) s = -INFINITY;

    float m = fmaxf(warpMax(s), 0.f);
    float p = (lane < cnt) ? expf(s - m) : 0.f;
    float denom = warpSum(p) + expf(-m);
    float inv = 1.f / denom;

    const float* vbase = g_qkv + (size_t)b * M_ * (3 * C_) + 2 * C_ + h * D_;
    float o0 = 0.f, o1 = 0.f;
    for (int j = 0; j < cnt; ++j) {
        float pj = __shfl_sync(0xffffffffu, p, j);
        int   kj = __shfl_sync(0xffffffffu, key_off, j);
        float2 vv = *(const float2*)(vbase + kj + 2 * lane);
        o0 += pj * vv.x;
        o1 += pj * vv.y;
    }
    float* op = g_att + ((size_t)b * M_ + (t + 1)) * C_ + h * D_;
    *(float2*)(op + 2 * lane) = make_float2(o0 * inv, o1 * inv);
}

// ---------------------------------------------------------------------------
// CLS attention, split-K.
// ---------------------------------------------------------------------------
__global__ void attn_cls_part_kernel() {
    int chunk = blockIdx.x;          // 0..7
    int bh    = blockIdx.y;          // 0..47
    int b = bh / H_, h = bh % H_;
    int start = chunk * 129;
    int end   = start + 129; if (end > 1025) end = 1025;
    int cnt   = end - start;
    int tid = threadIdx.x;           // 128

    __shared__ float sq[64];
    __shared__ float sc[132];
    __shared__ float sred[4];
    __shared__ float oacc[128];

    const float* qp = g_qkv + (size_t)(b * M_) * (3 * C_) + h * D_;
    if (tid < 64) sq[tid] = qp[tid];
    __syncthreads();

    for (int j = tid; j < cnt; j += 128) {
        const float* kp = g_qkv + ((size_t)b * M_ + start + j) * (3 * C_) + C_ + h * D_;
        float acc = 0.f;
#pragma unroll
        for (int d0 = 0; d0 < D_; d0 += 4) {
            float4 kv = *(const float4*)(kp + d0);
            acc += sq[d0] * kv.x + sq[d0 + 1] * kv.y + sq[d0 + 2] * kv.z + sq[d0 + 3] * kv.w;
        }
        sc[j] = acc * SCALE_;
    }
    __syncthreads();

    float m = -INFINITY;
    for (int j = tid; j < cnt; j += 128) m = fmaxf(m, sc[j]);
    m = warpMax(m);
    if ((tid & 31) == 0) sred[tid >> 5] = m;
    __syncthreads();
    m = fmaxf(fmaxf(sred[0], sred[1]), fmaxf(sred[2], sred[3]));
    __syncthreads();

    float ls = 0.f;
    for (int j = tid; j < cnt; j += 128) {
        float pv = expf(sc[j] - m);
        sc[j] = pv;
        ls += pv;
    }
    ls = warpSum(ls);
    if ((tid & 31) == 0) sred[tid >> 5] = ls;
    __syncthreads();
    float ssum = sred[0] + sred[1] + sred[2] + sred[3];

    int d = tid & 63, grp = tid >> 6;
    float acc = 0.f;
    for (int j = grp; j < cnt; j += 2)
        acc += sc[j] * g_qkv[((size_t)b * M_ + start + j) * (3 * C_) + 2 * C_ + h * D_ + d];
    oacc[tid] = acc;
    __syncthreads();

    float* dst = g_clsp + ((size_t)bh * 8 + chunk) * 66;
    if (tid < 64) dst[2 + tid] = oacc[tid] + oacc[tid + 64];
    if (tid == 0) { dst[0] = m; dst[1] = ssum; }
}

__global__ void attn_cls_comb_kernel() {
    int bh = blockIdx.x;             // 0..47
    int b = bh / H_, h = bh % H_;
    int d = threadIdx.x;             // 64
    const float* src = g_clsp + (size_t)bh * 8 * 66;
    float M = 0.f;
#pragma unroll
    for (int c = 0; c < 8; ++c) M = fmaxf(M, src[c * 66]);
    float denom = expf(-M);
    float o = 0.f;
#pragma unroll
    for (int c = 0; c < 8; ++c) {
        float w = expf(src[c * 66] - M);
        denom += src[c * 66 + 1] * w;
        o += src[c * 66 + 2 + d] * w;
    }
    g_att[(size_t)(b * M_) * C_ + h * D_ + d] = o / denom;
}

// Pad query: parallel over rows. grid (12, B), block 256.
__global__ void attn_pad_kernel() {
    int b = blockIdx.y;
    int cg = blockIdx.x;
    int tid = threadIdx.x;
    int cl = tid & 31;
    int rg = tid >> 5;
    int ch = cg * 32 + cl;
    const float* base = g_qkv + (size_t)b * M_ * (3 * C_) + 2 * C_ + ch;
    float acc = 0.f;
    for (int mrow = rg; mrow < 1025; mrow += 8)
        acc += base[(size_t)mrow * (3 * C_)];
    __shared__ float sm2[8][32];
    sm2[rg][cl] = acc;
    __syncthreads();
    if (tid < 32) {
        float a = 0.f;
#pragma unroll
        for (int rr = 0; rr < 8; ++rr) a += sm2[rr][tid];
        g_att[((size_t)b * M_ + 1025) * C_ + cg * 32 + tid] = a * (1.0f / 1026.0f);
    }
}

__global__ void concat_kernel() {
    int row = blockIdx.x;
    int b = row / CAT_, i = row % CAT_;
    const float* src = (i == 0) ? (g_h2 + (size_t)b * 1025 * C_)
                                : (g_tok + ((size_t)b * W_ + (i - 1)) * C_);
    float* dst = g_cat + (size_t)row * C_;
    for (int c = threadIdx.x; c < C_; c += blockDim.x) dst[c] = src[c];
}

// ---------------------------------------------------------------------------
// Launch
// ---------------------------------------------------------------------------
extern "C" void kernel_launch(void* const* d_in, const int* in_sizes, int n_in,
                              void* d_out, int out_size) {
    const float* x      = (const float*)d_in[0];
    const float* n1w    = (const float*)d_in[1];
    const float* n1b    = (const float*)d_in[2];
    const float* qkv_w  = (const float*)d_in[3];
    const float* proj_w = (const float*)d_in[4];
    const float* proj_b = (const float*)d_in[5];
    const float* n2w    = (const float*)d_in[6];
    const float* n2b    = (const float*)d_in[7];
    const float* pool_w = (const float*)d_in[8];
    const float* pool_b = (const float*)d_in[9];
    const float* n3w    = (const float*)d_in[10];
    const float* n3b    = (const float*)d_in[11];
    const float* fc1_w  = (const float*)d_in[12];
    const float* fc1_b  = (const float*)d_in[13];
    const float* fc2_w  = (const float*)d_in[14];
    const float* fc2_b  = (const float*)d_in[15];
    float* out = (float*)d_out;

    float *h1, *qkvp, *att, *res, *h2, *tok, *cat, *h3, *fc1o;
    cudaGetSymbolAddress((void**)&h1,   g_h1);
    cudaGetSymbolAddress((void**)&qkvp, g_qkv);
    cudaGetSymbolAddress((void**)&att,  g_att);
    cudaGetSymbolAddress((void**)&res,  g_res);
    cudaGetSymbolAddress((void**)&h2,   g_h2);
    cudaGetSymbolAddress((void**)&tok,  g_tok);
    cudaGetSymbolAddress((void**)&cat,  g_cat);
    cudaGetSymbolAddress((void**)&h3,   g_h3);
    cudaGetSymbolAddress((void**)&fc1o, g_fc1);

    static int smemSet = 0;
    if (!smemSet) {
        cudaFuncSetAttribute(tgemm_kernel<0>,
                             cudaFuncAttributeMaxDynamicSharedMemorySize, TG_SMEM);
        cudaFuncSetAttribute(tgemm_kernel<1>,
                             cudaFuncAttributeMaxDynamicSharedMemorySize, TG_SMEM);
        smemSet = 1;
    }

    const int MROWS = B_ * M_;        // 8208
    const int PROWS = B_ * W_;        // 2048
    const int CROWS = B_ * CAT_;      // 2056

    key_precompute_kernel<<<1, 1024>>>();
    ln_kernel<<<dim3(1025, B_), 128>>>(x, h1, n1w, n1b, 1025, M_);
    zero_pad_kernel<<<B_, C_>>>();

    tgemm_kernel<0><<<dim3(1152 / 64, (MROWS + 127) / 128), 256, TG_SMEM>>>(
        MROWS, 3 * C_, C_, h1, qkv_w, nullptr, nullptr, qkvp, 0);

    attn_token_kernel<<<(B_ * H_ * NT_) / 8, 256>>>();
    attn_cls_part_kernel<<<dim3(8, B_ * H_), 128>>>();
    attn_cls_comb_kernel<<<B_ * H_, 64>>>();
    attn_pad_kernel<<<dim3(12, B_), 256>>>();

    tgemm_kernel<0><<<dim3(C_ / 64, (MROWS + 127) / 128), 256, TG_SMEM>>>(
        MROWS, C_, C_, att, proj_w, proj_b, h1, res, 0);

    ln_kernel<<<dim3(1025, B_), 128>>>(res, h2, n2w, n2b, M_, 1025);

    // pool GEMM with fused window gather (A = g_h2)
    tgemm_kernel<1><<<dim3(C_ / 64, PROWS / 128), 256, TG_SMEM>>>(
        PROWS, C_, 9 * C_, h2, pool_w, pool_b, nullptr, tok, 0);

    concat_kernel<<<B_ * CAT_, 128>>>();
    ln_kernel<<<dim3(CAT_, B_), 128>>>(cat, h3, n3w, n3b, CAT_, CAT_);

    tgemm_kernel<0><<<dim3(HID_ / 64, (CROWS + 127) / 128), 256, TG_SMEM>>>(
        CROWS, HID_, C_, h3, fc1_w, fc1_b, nullptr, fc1o, 1);
    tgemm_kernel<0><<<dim3(C_ / 64, (CROWS + 127) / 128), 256, TG_SMEM>>>(
        CROWS, C_, HID_, fc1o, fc2_w, fc2_b, nullptr, out, 0);
}

// round 14
// speedup vs baseline: 1.1967x; 1.0685x over previous
#include <cuda_runtime.h>
#include <math.h>

#define B_    8
#define M_    1026
#define NT_   1024
#define C_    384
#define H_    6
#define D_    64
#define HID_  1536
#define W_    256
#define CAT_  257
#define SCALE_ 0.4082482904638631f

// ---------------------------------------------------------------------------
// Scratch
// ---------------------------------------------------------------------------
__device__ float g_h1  [B_*M_*C_];        // LN1 exact (proj residual)
__device__ float g_h1r [B_*M_*C_];        // LN1 tf32-rounded (QKV GEMM A)
__device__ float g_qkv [B_*M_*3*C_];
__device__ float g_att [B_*M_*C_];        // tf32-rounded at write
__device__ float g_res [B_*M_*C_];
__device__ float g_h2  [B_*(NT_+1)*C_];   // tf32-rounded (pool GEMM A)
__device__ float g_tok [B_*W_*C_];
__device__ float g_cat [B_*CAT_*C_];
__device__ float g_h3  [B_*CAT_*C_];      // tf32-rounded (fc1 GEMM A)
__device__ float g_fc1 [B_*CAT_*HID_];    // tf32-rounded (fc2 GEMM A)
__device__ float g_clsp[48*8*66];
// pre-rounded weights
__device__ float g_wqkv [3*C_*C_];
__device__ float g_wproj[C_*C_];
__device__ float g_wpool[C_*9*C_];
__device__ float g_wfc1 [HID_*C_];
__device__ float g_wfc2 [C_*HID_];
// precomputed sparse-attention key table
__device__ int   g_keys[NT_*32];
__device__ int   g_kcnt[NT_];

// ---------------------------------------------------------------------------
// Helpers
// ---------------------------------------------------------------------------
__device__ __forceinline__ float warpSum(float v) {
#pragma unroll
    for (int o = 16; o > 0; o >>= 1) v += __shfl_xor_sync(0xffffffffu, v, o);
    return v;
}
__device__ __forceinline__ float warpMax(float v) {
#pragma unroll
    for (int o = 16; o > 0; o >>= 1) v = fmaxf(v, __shfl_xor_sync(0xffffffffu, v, o));
    return v;
}
__device__ __forceinline__ unsigned f2tf(float f) {
    unsigned u;
    asm("cvt.rna.tf32.f32 %0, %1;" : "=r"(u) : "f"(f));
    return u;
}
__device__ __forceinline__ float rtf(float f) { return __uint_as_float(f2tf(f)); }
__device__ __forceinline__ void cpasync16(void* smem_dst, const void* gsrc, bool pred) {
    unsigned saddr = (unsigned)__cvta_generic_to_shared(smem_dst);
    int sz = pred ? 16 : 0;
    asm volatile("cp.async.ca.shared.global [%0], [%1], 16, %2;\n"
                 :: "r"(saddr), "l"(gsrc), "r"(sz));
}
__device__ __forceinline__ void ldsm4(unsigned& r0, unsigned& r1, unsigned& r2, unsigned& r3,
                                      unsigned addr) {
    asm volatile("ldmatrix.sync.aligned.m8n8.x4.shared.b16 {%0,%1,%2,%3}, [%4];\n"
                 : "=r"(r0), "=r"(r1), "=r"(r2), "=r"(r3) : "r"(addr));
}

// ---------------------------------------------------------------------------
// Merged weight pre-rounding: ALL weights in one launch (one wave, ~5us).
// Segment prefix (float4 units): qkv 110592 | proj 36864 | pool 331776 |
// fc1 147456 | fc2 147456; total 774144.
// ---------------------------------------------------------------------------
#define WQ4 110592
#define WP4 36864
#define WO4 331776
#define W14 147456
#define W24 147456
#define WT4 (WQ4+WP4+WO4+W14+W24)   // 774144

__global__ void wround_kernel(const float4* __restrict__ qkv,
                              const float4* __restrict__ proj,
                              const float4* __restrict__ pool,
                              const float4* __restrict__ f1,
                              const float4* __restrict__ f2) {
    int i = blockIdx.x * 256 + threadIdx.x;
    if (i >= WT4) return;
    const float4* src;
    float4* dst;
    int o = i;
    if (o < WQ4)                       { src = qkv  + o; dst = (float4*)g_wqkv  + o; }
    else if ((o -= WQ4) < WP4)         { src = proj + o; dst = (float4*)g_wproj + o; }
    else if ((o -= WP4) < WO4)         { src = pool + o; dst = (float4*)g_wpool + o; }
    else if ((o -= WO4) < W14)         { src = f1   + o; dst = (float4*)g_wfc1  + o; }
    else { o -= W14;                     src = f2   + o; dst = (float4*)g_wfc2  + o; }
    float4 v = *src;
    *dst = make_float4(rtf(v.x), rtf(v.y), rtf(v.z), rtf(v.w));
}

// ---------------------------------------------------------------------------
// Key table precompute
// ---------------------------------------------------------------------------
__global__ void key_precompute_kernel() {
    int t = threadIdx.x;
    int r = t >> 5, c = t & 31;
    int rl[5], cl[5];
    int nr = 0, nc = 0;
#pragma unroll
    for (int dr = -2; dr <= 2; ++dr) {
        int rp = r + dr;
        if (rp < 0 || rp > 31) continue;
        int lo = (r > rp ? r : rp) - 1; if (lo < 0) lo = 0;
        int hi = (r < rp ? r : rp) + 1; if (hi > 30) hi = 30;
        int fe = lo + (lo & 1);
        if (fe <= hi) rl[nr++] = rp;
    }
#pragma unroll
    for (int dc = -2; dc <= 2; ++dc) {
        int cp = c + dc;
        if (cp < 0 || cp > 31) continue;
        int lo = (c > cp ? c : cp) - 1; if (lo < 0) lo = 0;
        int hi = (c < cp ? c : cp) + 1; if (hi > 30) hi = 30;
        int fe = lo + (lo & 1);
        if (fe <= hi) cl[nc++] = cp;
    }
    int cnt = 1 + nr * nc;
    g_kcnt[t] = cnt;
    for (int j = 0; j < 32; ++j) {
        int key = 0;
        if (j >= 1 && j < cnt) {
            int i = j - 1;
            key = rl[i / nc] * 32 + cl[i % nc] + 1;
        }
        g_keys[t * 32 + j] = key * (3 * C_);
    }
}

// ---------------------------------------------------------------------------
// LayerNorm; roundMain rounds output to tf32 grid; outR = extra rounded copy
// ---------------------------------------------------------------------------
__global__ void ln_kernel(const float* __restrict__ in, float* __restrict__ out,
                          const float* __restrict__ gw, const float* __restrict__ gb,
                          int inStride, int outStride, int roundMain,
                          float* __restrict__ outR) {
    int i = blockIdx.x, b = blockIdx.y;
    const float* xr = in + ((size_t)b * inStride + i) * C_;
    float* yr = out + ((size_t)b * outStride + i) * C_;
    int tid = threadIdx.x;
    float v0 = xr[tid], v1 = xr[tid + 128], v2 = xr[tid + 256];
    __shared__ float sm[4];
    float s = warpSum(v0 + v1 + v2);
    if ((tid & 31) == 0) sm[tid >> 5] = s;
    __syncthreads();
    float mu = (sm[0] + sm[1] + sm[2] + sm[3]) * (1.f / 384.f);
    float d0 = v0 - mu, d1 = v1 - mu, d2 = v2 - mu;
    __syncthreads();
    float q = warpSum(d0 * d0 + d1 * d1 + d2 * d2);
    if ((tid & 31) == 0) sm[tid >> 5] = q;
    __syncthreads();
    float var = (sm[0] + sm[1] + sm[2] + sm[3]) * (1.f / 384.f);
    float rs = rsqrtf(var + 1e-5f);
    float r0 = d0 * rs * gw[tid]       + gb[tid];
    float r1 = d1 * rs * gw[tid + 128] + gb[tid + 128];
    float r2 = d2 * rs * gw[tid + 256] + gb[tid + 256];
    if (roundMain) { r0 = rtf(r0); r1 = rtf(r1); r2 = rtf(r2); }
    yr[tid]       = r0;
    yr[tid + 128] = r1;
    yr[tid + 256] = r2;
    if (outR) {
        float* zr = outR + ((size_t)b * outStride + i) * C_;
        zr[tid]       = rtf(r0);
        zr[tid + 128] = rtf(r1);
        zr[tid + 256] = rtf(r2);
    }
}

__global__ void zero_pad_kernel() {
    size_t off = ((size_t)blockIdx.x * M_ + 1025) * C_ + threadIdx.x;
    g_h1[off]  = 0.f;
    g_h1r[off] = 0.f;
}

// ---------------------------------------------------------------------------
// TF32 tensor-core GEMM: 128x64x32, 256 threads, 2-stage cp.async,
// ldmatrix.x4 fragment loads, CVT-FREE mainloop (all inputs pre-rounded
// to the tf32 grid by producers -> LDSM feeds MMA directly).
// roundOut rounds stored values (for GEMM-feeding outputs, e.g. fc1-gelu).
// ---------------------------------------------------------------------------
#define KP_ 36
#define TG_SMEM ((2*128*KP_ + 2*64*KP_) * 4)   // 55296 bytes
#define SA_STAGE_BYTES (128*KP_*4)
#define SB_STAGE_BYTES (64*KP_*4)
#define SB_BASE_BYTES  (2*128*KP_*4)

template<int GATHER>
__global__ void __launch_bounds__(256)
tgemm_kernel(int M, int N, int K,
             const float* __restrict__ A, const float* __restrict__ Wt,
             const float* __restrict__ bias, const float* __restrict__ resid,
             float* __restrict__ Cc, int doGelu, int roundOut) {
    extern __shared__ float dyn[];
    float (*sA)[128][KP_] = (float(*)[128][KP_])dyn;
    float (*sB)[64][KP_]  = (float(*)[64][KP_])(dyn + 2 * 128 * KP_);

    int tid  = threadIdx.x;
    int lane = tid & 31;
    int wid  = tid >> 5;
    int wm   = wid & 3;
    int wn   = wid >> 2;
    int lr   = lane >> 2;
    int lc   = lane & 3;

    int bm = blockIdx.y * 128;
    int bn = blockIdx.x * 64;

    int ldRow = tid >> 3;
    int ldC4  = tid & 7;

    unsigned smemU = (unsigned)__cvta_generic_to_shared(dyn);
    int lm = lane >> 3;
    int lrr = lane & 7;
    unsigned aAddr[2];
#pragma unroll
    for (int mt = 0; mt < 2; ++mt)
        aAddr[mt] = smemU +
            ((unsigned)((wm * 32 + mt * 16 + (lm & 1) * 8 + lrr) * KP_ + (lm >> 1) * 4)) * 4u;
    unsigned bAddr = smemU + SB_BASE_BYTES +
        ((unsigned)((wn * 32 + lm * 8 + lrr) * KP_)) * 4u;

    float acc[2][4][4];
#pragma unroll
    for (int mt = 0; mt < 2; ++mt)
#pragma unroll
        for (int nt = 0; nt < 4; ++nt)
#pragma unroll
            for (int e = 0; e < 4; ++e) acc[mt][nt][e] = 0.f;

    int nIter = K >> 5;

    auto loadTile = [&](int it, int s) {
        int k0 = it << 5;
        if (!GATHER) {
#pragma unroll
            for (int i = 0; i < 4; ++i) {
                int r = ldRow + i * 32;
                int gr = bm + r;
                bool p = gr < M;
                const float* src = A + (size_t)(p ? gr : 0) * K + k0 + ldC4 * 4;
                cpasync16(&sA[s][r][ldC4 * 4], src, p);
            }
        } else {
            int kk = k0 / 384;
            int c0 = k0 - kk * 384;
#pragma unroll
            for (int i = 0; i < 4; ++i) {
                int r = ldRow + i * 32;
                int gr = bm + r;
                int b = gr >> 8, w = gr & 255;
                int wi = w >> 4, wj = w & 15;
                int rr = 2 * wi + kk / 3 - 1;
                int cc = 2 * wj + kk % 3 - 1;
                int hrow = (rr < 0 || cc < 0) ? 1024 : rr * 32 + cc + 1;
                const float* src = A + ((size_t)b * 1025 + hrow) * 384 + c0 + ldC4 * 4;
                cpasync16(&sA[s][r][ldC4 * 4], src, true);
            }
        }
#pragma unroll
        for (int i = 0; i < 2; ++i) {
            int n = ldRow + i * 32;
            int gn = bn + n;
            bool p = gn < N;
            const float* src = Wt + (size_t)(p ? gn : 0) * K + k0 + ldC4 * 4;
            cpasync16(&sB[s][n][ldC4 * 4], src, p);
        }
    };

    loadTile(0, 0);
    asm volatile("cp.async.commit_group;\n");

    for (int it = 0; it < nIter; ++it) {
        int s = it & 1;
        if (it + 1 < nIter) {
            loadTile(it + 1, s ^ 1);
            asm volatile("cp.async.commit_group;\n");
            asm volatile("cp.async.wait_group 1;\n");
        } else {
            asm volatile("cp.async.wait_group 0;\n");
        }
        __syncthreads();

        unsigned sAoff = (unsigned)(s * SA_STAGE_BYTES);
        unsigned sBoff = (unsigned)(s * SB_STAGE_BYTES);

#pragma unroll
        for (int ks = 0; ks < 4; ++ks) {
            unsigned kOff = (unsigned)(ks * 8 * 4);
            unsigned a[2][4], bf[4][2];
#pragma unroll
            for (int mt = 0; mt < 2; ++mt)
                ldsm4(a[mt][0], a[mt][1], a[mt][2], a[mt][3],
                      aAddr[mt] + sAoff + kOff);
            {
                unsigned b0, b1, b2, b3;
                ldsm4(b0, b1, b2, b3, bAddr + sBoff + kOff);
                bf[0][0] = b0; bf[1][0] = b1; bf[2][0] = b2; bf[3][0] = b3;
                ldsm4(b0, b1, b2, b3, bAddr + sBoff + kOff + 16);
                bf[0][1] = b0; bf[1][1] = b1; bf[2][1] = b2; bf[3][1] = b3;
            }
            // no cvt: inputs already on the tf32 grid
#pragma unroll
            for (int mt = 0; mt < 2; ++mt)
#pragma unroll
                for (int nt = 0; nt < 4; ++nt) {
                    asm volatile(
                        "mma.sync.aligned.m16n8k8.row.col.f32.tf32.tf32.f32 "
                        "{%0,%1,%2,%3}, {%4,%5,%6,%7}, {%8,%9}, {%0,%1,%2,%3};\n"
                        : "+f"(acc[mt][nt][0]), "+f"(acc[mt][nt][1]),
                          "+f"(acc[mt][nt][2]), "+f"(acc[mt][nt][3])
                        : "r"(a[mt][0]), "r"(a[mt][1]), "r"(a[mt][2]), "r"(a[mt][3]),
                          "r"(bf[nt][0]), "r"(bf[nt][1]));
                }
        }
        __syncthreads();
    }

#pragma unroll
    for (int mt = 0; mt < 2; ++mt) {
#pragma unroll
        for (int nt = 0; nt < 4; ++nt) {
            int col = bn + wn * 32 + nt * 8 + 2 * lc;
            float bx = 0.f, by = 0.f;
            if (bias) { bx = bias[col]; by = bias[col + 1]; }
#pragma unroll
            for (int half = 0; half < 2; ++half) {
                int row = bm + wm * 32 + mt * 16 + lr + half * 8;
                if (row >= M) continue;
                float vx = acc[mt][nt][2 * half + 0] + bx;
                float vy = acc[mt][nt][2 * half + 1] + by;
                if (resid) {
                    const float2 rv = *(const float2*)(resid + (size_t)row * N + col);
                    vx += rv.x; vy += rv.y;
                }
                if (doGelu) {
                    vx = 0.5f * vx * (1.f + erff(vx * 0.70710678118654752f));
                    vy = 0.5f * vy * (1.f + erff(vy * 0.70710678118654752f));
                }
                if (roundOut) { vx = rtf(vx); vy = rtf(vy); }
                *(float2*)(Cc + (size_t)row * N + col) = make_float2(vx, vy);
            }
        }
    }
}

// ---------------------------------------------------------------------------
// Sparse attention (token queries); outputs rounded for the proj GEMM.
// ---------------------------------------------------------------------------
__global__ void attn_token_kernel() {
    int gw = (blockIdx.x * blockDim.x + threadIdx.x) >> 5;
    int lane = threadIdx.x & 31;
    int t  = gw & 1023;
    int bh = gw >> 10;
    int h = bh % H_;
    int b = bh / H_;

    int key_off = g_keys[t * 32 + lane];
    int cnt     = g_kcnt[t];

    const float* qp = g_qkv + ((size_t)b * M_ + (t + 1)) * (3 * C_) + h * D_;
    int hl = lane & 15;
    float4 qv = *(const float4*)(qp + hl * 4);
    const float* kbase = g_qkv + (size_t)b * M_ * (3 * C_) + C_ + h * D_;

    float s = -INFINITY;
    for (int j0 = 0; j0 < 26; j0 += 2) {
        if (j0 >= cnt) break;
        int ka = __shfl_sync(0xffffffffu, key_off, j0);
        int kb = __shfl_sync(0xffffffffu, key_off, j0 + 1);
        int kidx = (lane < 16) ? ka : kb;
        float4 kv = *(const float4*)(kbase + kidx + hl * 4);
        float d = qv.x * kv.x + qv.y * kv.y + qv.z * kv.z + qv.w * kv.w;
        d += __shfl_xor_sync(0xffffffffu, d, 8);
        d += __shfl_xor_sync(0xffffffffu, d, 4);
        d += __shfl_xor_sync(0xffffffffu, d, 2);
        d += __shfl_xor_sync(0xffffffffu, d, 1);
        float dx = __shfl_xor_sync(0xffffffffu, d, 16);
        float da = (lane < 16) ? d : dx;
        float db = (lane < 16) ? dx : d;
        if (lane == j0)     s = da * SCALE_;
        if (lane == j0 + 1) s = db * SCALE_;
    }
    if (lane >= cnt) s = -INFINITY;

    float m = fmaxf(warpMax(s), 0.f);
    float p = (lane < cnt) ? expf(s - m) : 0.f;
    float denom = warpSum(p) + expf(-m);
    float inv = 1.f / denom;

    const float* vbase = g_qkv + (size_t)b * M_ * (3 * C_) + 2 * C_ + h * D_;
    float o0 = 0.f, o1 = 0.f;
    for (int j = 0; j < cnt; ++j) {
        float pj = __shfl_sync(0xffffffffu, p, j);
        int   kj = __shfl_sync(0xffffffffu, key_off, j);
        float2 vv = *(const float2*)(vbase + kj + 2 * lane);
        o0 += pj * vv.x;
        o1 += pj * vv.y;
    }
    float* op = g_att + ((size_t)b * M_ + (t + 1)) * C_ + h * D_;
    *(float2*)(op + 2 * lane) = make_float2(rtf(o0 * inv), rtf(o1 * inv));
}

// ---------------------------------------------------------------------------
// CLS attention, split-K.
// ---------------------------------------------------------------------------
__global__ void attn_cls_part_kernel() {
    int chunk = blockIdx.x;
    int bh    = blockIdx.y;
    int b = bh / H_, h = bh % H_;
    int start = chunk * 129;
    int end   = start + 129; if (end > 1025) end = 1025;
    int cnt   = end - start;
    int tid = threadIdx.x;

    __shared__ float sq[64];
    __shared__ float sc[132];
    __shared__ float sred[4];
    __shared__ float oacc[128];

    const float* qp = g_qkv + (size_t)(b * M_) * (3 * C_) + h * D_;
    if (tid < 64) sq[tid] = qp[tid];
    __syncthreads();

    for (int j = tid; j < cnt; j += 128) {
        const float* kp = g_qkv + ((size_t)b * M_ + start + j) * (3 * C_) + C_ + h * D_;
        float acc = 0.f;
#pragma unroll
        for (int d0 = 0; d0 < D_; d0 += 4) {
            float4 kv = *(const float4*)(kp + d0);
            acc += sq[d0] * kv.x + sq[d0 + 1] * kv.y + sq[d0 + 2] * kv.z + sq[d0 + 3] * kv.w;
        }
        sc[j] = acc * SCALE_;
    }
    __syncthreads();

    float m = -INFINITY;
    for (int j = tid; j < cnt; j += 128) m = fmaxf(m, sc[j]);
    m = warpMax(m);
    if ((tid & 31) == 0) sred[tid >> 5] = m;
    __syncthreads();
    m = fmaxf(fmaxf(sred[0], sred[1]), fmaxf(sred[2], sred[3]));
    __syncthreads();

    float ls = 0.f;
    for (int j = tid; j < cnt; j += 128) {
        float pv = expf(sc[j] - m);
        sc[j] = pv;
        ls += pv;
    }
    ls = warpSum(ls);
    if ((tid & 31) == 0) sred[tid >> 5] = ls;
    __syncthreads();
    float ssum = sred[0] + sred[1] + sred[2] + sred[3];

    int d = tid & 63, grp = tid >> 6;
    float acc = 0.f;
    for (int j = grp; j < cnt; j += 2)
        acc += sc[j] * g_qkv[((size_t)b * M_ + start + j) * (3 * C_) + 2 * C_ + h * D_ + d];
    oacc[tid] = acc;
    __syncthreads();

    float* dst = g_clsp + ((size_t)bh * 8 + chunk) * 66;
    if (tid < 64) dst[2 + tid] = oacc[tid] + oacc[tid + 64];
    if (tid == 0) { dst[0] = m; dst[1] = ssum; }
}

__global__ void attn_cls_comb_kernel() {
    int bh = blockIdx.x;
    int b = bh / H_, h = bh % H_;
    int d = threadIdx.x;
    const float* src = g_clsp + (size_t)bh * 8 * 66;
    float M = 0.f;
#pragma unroll
    for (int c = 0; c < 8; ++c) M = fmaxf(M, src[c * 66]);
    float denom = expf(-M);
    float o = 0.f;
#pragma unroll
    for (int c = 0; c < 8; ++c) {
        float w = expf(src[c * 66] - M);
        denom += src[c * 66 + 1] * w;
        o += src[c * 66 + 2 + d] * w;
    }
    g_att[(size_t)(b * M_) * C_ + h * D_ + d] = rtf(o / denom);
}

// Pad query.
__global__ void attn_pad_kernel() {
    int b = blockIdx.y;
    int cg = blockIdx.x;
    int tid = threadIdx.x;
    int cl = tid & 31;
    int rg = tid >> 5;
    int ch = cg * 32 + cl;
    const float* base = g_qkv + (size_t)b * M_ * (3 * C_) + 2 * C_ + ch;
    float acc = 0.f;
    for (int mrow = rg; mrow < 1025; mrow += 8)
        acc += base[(size_t)mrow * (3 * C_)];
    __shared__ float sm2[8][32];
    sm2[rg][cl] = acc;
    __syncthreads();
    if (tid < 32) {
        float a = 0.f;
#pragma unroll
        for (int rr = 0; rr < 8; ++rr) a += sm2[rr][tid];
        g_att[((size_t)b * M_ + 1025) * C_ + cg * 32 + tid] = rtf(a * (1.0f / 1026.0f));
    }
}

__global__ void concat_kernel() {
    int row = blockIdx.x;
    int b = row / CAT_, i = row % CAT_;
    const float* src = (i == 0) ? (g_h2 + (size_t)b * 1025 * C_)
                                : (g_tok + ((size_t)b * W_ + (i - 1)) * C_);
    float* dst = g_cat + (size_t)row * C_;
    for (int c = threadIdx.x; c < C_; c += blockDim.x) dst[c] = src[c];
}

// ---------------------------------------------------------------------------
// Launch
// ---------------------------------------------------------------------------
extern "C" void kernel_launch(void* const* d_in, const int* in_sizes, int n_in,
                              void* d_out, int out_size) {
    const float* x      = (const float*)d_in[0];
    const float* n1w    = (const float*)d_in[1];
    const float* n1b    = (const float*)d_in[2];
    const float* qkv_w  = (const float*)d_in[3];
    const float* proj_w = (const float*)d_in[4];
    const float* proj_b = (const float*)d_in[5];
    const float* n2w    = (const float*)d_in[6];
    const float* n2b    = (const float*)d_in[7];
    const float* pool_w = (const float*)d_in[8];
    const float* pool_b = (const float*)d_in[9];
    const float* n3w    = (const float*)d_in[10];
    const float* n3b    = (const float*)d_in[11];
    const float* fc1_w  = (const float*)d_in[12];
    const float* fc1_b  = (const float*)d_in[13];
    const float* fc2_w  = (const float*)d_in[14];
    const float* fc2_b  = (const float*)d_in[15];
    float* out = (float*)d_out;

    float *h1, *h1r, *qkvp, *att, *res, *h2, *tok, *cat, *h3, *fc1o;
    float *wqkv, *wproj, *wpool, *wfc1, *wfc2;
    cudaGetSymbolAddress((void**)&h1,    g_h1);
    cudaGetSymbolAddress((void**)&h1r,   g_h1r);
    cudaGetSymbolAddress((void**)&qkvp,  g_qkv);
    cudaGetSymbolAddress((void**)&att,   g_att);
    cudaGetSymbolAddress((void**)&res,   g_res);
    cudaGetSymbolAddress((void**)&h2,    g_h2);
    cudaGetSymbolAddress((void**)&tok,   g_tok);
    cudaGetSymbolAddress((void**)&cat,   g_cat);
    cudaGetSymbolAddress((void**)&h3,    g_h3);
    cudaGetSymbolAddress((void**)&fc1o,  g_fc1);
    cudaGetSymbolAddress((void**)&wqkv,  g_wqkv);
    cudaGetSymbolAddress((void**)&wproj, g_wproj);
    cudaGetSymbolAddress((void**)&wpool, g_wpool);
    cudaGetSymbolAddress((void**)&wfc1,  g_wfc1);
    cudaGetSymbolAddress((void**)&wfc2,  g_wfc2);

    static int smemSet = 0;
    if (!smemSet) {
        cudaFuncSetAttribute(tgemm_kernel<0>,
                             cudaFuncAttributeMaxDynamicSharedMemorySize, TG_SMEM);
        cudaFuncSetAttribute(tgemm_kernel<1>,
                             cudaFuncAttributeMaxDynamicSharedMemorySize, TG_SMEM);
        smemSet = 1;
    }

    const int MROWS = B_ * M_;        // 8208
    const int PROWS = B_ * W_;        // 2048
    const int CROWS = B_ * CAT_;      // 2056

    wround_kernel<<<(WT4 + 255) / 256, 256>>>(
        (const float4*)qkv_w, (const float4*)proj_w, (const float4*)pool_w,
        (const float4*)fc1_w, (const float4*)fc2_w);
    key_precompute_kernel<<<1, 1024>>>();

    // LN1: exact -> h1 (residual), rounded copy -> h1r (QKV A)
    ln_kernel<<<dim3(1025, B_), 128>>>(x, h1, n1w, n1b, 1025, M_, 0, h1r);
    zero_pad_kernel<<<B_, C_>>>();

    tgemm_kernel<0><<<dim3(1152 / 64, (MROWS + 127) / 128), 256, TG_SMEM>>>(
        MROWS, 3 * C_, C_, h1r, wqkv, nullptr, nullptr, qkvp, 0, 0);

    attn_token_kernel<<<(B_ * H_ * NT_) / 8, 256>>>();
    attn_cls_part_kernel<<<dim3(8, B_ * H_), 128>>>();
    attn_cls_comb_kernel<<<B_ * H_, 64>>>();
    attn_pad_kernel<<<dim3(12, B_), 256>>>();

    tgemm_kernel<0><<<dim3(C_ / 64, (MROWS + 127) / 128), 256, TG_SMEM>>>(
        MROWS, C_, C_, att, wproj, proj_b, h1, res, 0, 0);

    // LN2 output rounded (pool GEMM A)
    ln_kernel<<<dim3(1025, B_), 128>>>(res, h2, n2w, n2b, M_, 1025, 1, nullptr);

    tgemm_kernel<1><<<dim3(C_ / 64, PROWS / 128), 256, TG_SMEM>>>(
        PROWS, C_, 9 * C_, h2, wpool, pool_b, nullptr, tok, 0, 0);

    concat_kernel<<<B_ * CAT_, 128>>>();
    // LN3 output rounded (fc1 GEMM A)
    ln_kernel<<<dim3(CAT_, B_), 128>>>(cat, h3, n3w, n3b, CAT_, CAT_, 1, nullptr);

    tgemm_kernel<0><<<dim3(HID_ / 64, (CROWS + 127) / 128), 256, TG_SMEM>>>(
        CROWS, HID_, C_, h3, wfc1, fc1_b, nullptr, fc1o, 1, 1);
    tgemm_kernel<0><<<dim3(C_ / 64, (CROWS + 127) / 128), 256, TG_SMEM>>>(
        CROWS, C_, HID_, fc1o, wfc2, fc2_b, nullptr, out, 0, 0);
}

// round 15
// speedup vs baseline: 1.2616x; 1.0542x over previous
#include <cuda_runtime.h>
#include <math.h>

#define B_    8
#define M_    1026
#define NT_   1024
#define C_    384
#define H_    6
#define D_    64
#define HID_  1536
#define W_    256
#define CAT_  257
#define SCALE_ 0.4082482904638631f

// ---------------------------------------------------------------------------
// Scratch
// ---------------------------------------------------------------------------
__device__ float g_h1  [B_*M_*C_];        // LN1 exact (proj residual)
__device__ float g_h1r [B_*M_*C_];        // LN1 tf32-rounded (QKV GEMM A)
__device__ float g_qkv [B_*M_*3*C_];
__device__ float g_att [B_*M_*C_];        // tf32-rounded at write
__device__ float g_res [B_*M_*C_];
__device__ float g_h2  [B_*(NT_+1)*C_];   // tf32-rounded (pool GEMM A)
__device__ float g_cat [B_*CAT_*C_];
__device__ float g_h3  [B_*CAT_*C_];      // tf32-rounded (fc1 GEMM A)
__device__ float g_fc1 [B_*CAT_*HID_];    // tf32-rounded (fc2 GEMM A)
__device__ float g_clsp[48*8*66];
// pre-rounded weights
__device__ float g_wqkv [3*C_*C_];
__device__ float g_wproj[C_*C_];
__device__ float g_wpool[C_*9*C_];
__device__ float g_wfc1 [HID_*C_];
__device__ float g_wfc2 [C_*HID_];
// precomputed sparse-attention key table
__device__ int   g_keys[NT_*32];
__device__ int   g_kcnt[NT_];

// ---------------------------------------------------------------------------
// Helpers
// ---------------------------------------------------------------------------
__device__ __forceinline__ float warpSum(float v) {
#pragma unroll
    for (int o = 16; o > 0; o >>= 1) v += __shfl_xor_sync(0xffffffffu, v, o);
    return v;
}
__device__ __forceinline__ float warpMax(float v) {
#pragma unroll
    for (int o = 16; o > 0; o >>= 1) v = fmaxf(v, __shfl_xor_sync(0xffffffffu, v, o));
    return v;
}
__device__ __forceinline__ unsigned f2tf(float f) {
    unsigned u;
    asm("cvt.rna.tf32.f32 %0, %1;" : "=r"(u) : "f"(f));
    return u;
}
__device__ __forceinline__ float rtf(float f) { return __uint_as_float(f2tf(f)); }
__device__ __forceinline__ void cpasync16(void* smem_dst, const void* gsrc, bool pred) {
    unsigned saddr = (unsigned)__cvta_generic_to_shared(smem_dst);
    int sz = pred ? 16 : 0;
    asm volatile("cp.async.ca.shared.global [%0], [%1], 16, %2;\n"
                 :: "r"(saddr), "l"(gsrc), "r"(sz));
}
__device__ __forceinline__ void ldsm4(unsigned& r0, unsigned& r1, unsigned& r2, unsigned& r3,
                                      unsigned addr) {
    asm volatile("ldmatrix.sync.aligned.m8n8.x4.shared.b16 {%0,%1,%2,%3}, [%4];\n"
                 : "=r"(r0), "=r"(r1), "=r"(r2), "=r"(r3) : "r"(addr));
}

// ---------------------------------------------------------------------------
// Merged prep: weight rounding (blocks 0..WB-1) + key table (last 4 blocks).
// ---------------------------------------------------------------------------
#define WQ4 110592
#define WP4 36864
#define WO4 331776
#define W14 147456
#define W24 147456
#define WT4 (WQ4+WP4+WO4+W14+W24)   // 774144
#define WB_ ((WT4 + 255) / 256)     // 3024

__global__ void prep_kernel(const float4* __restrict__ qkv,
                            const float4* __restrict__ proj,
                            const float4* __restrict__ pool,
                            const float4* __restrict__ f1,
                            const float4* __restrict__ f2) {
    int blk = blockIdx.x;
    int tid = threadIdx.x;
    if (blk < WB_) {
        int i = blk * 256 + tid;
        if (i >= WT4) return;
        const float4* src;
        float4* dst;
        int o = i;
        if (o < WQ4)               { src = qkv  + o; dst = (float4*)g_wqkv  + o; }
        else if ((o -= WQ4) < WP4) { src = proj + o; dst = (float4*)g_wproj + o; }
        else if ((o -= WP4) < WO4) { src = pool + o; dst = (float4*)g_wpool + o; }
        else if ((o -= WO4) < W14) { src = f1   + o; dst = (float4*)g_wfc1  + o; }
        else { o -= W14;             src = f2   + o; dst = (float4*)g_wfc2  + o; }
        float4 v = *src;
        *dst = make_float4(rtf(v.x), rtf(v.y), rtf(v.z), rtf(v.w));
        return;
    }
    // key-table blocks: t in [0, 1024)
    int t = (blk - WB_) * 256 + tid;
    int r = t >> 5, c = t & 31;
    int rl[5], cl[5];
    int nr = 0, nc = 0;
#pragma unroll
    for (int dr = -2; dr <= 2; ++dr) {
        int rp = r + dr;
        if (rp < 0 || rp > 31) continue;
        int lo = (r > rp ? r : rp) - 1; if (lo < 0) lo = 0;
        int hi = (r < rp ? r : rp) + 1; if (hi > 30) hi = 30;
        int fe = lo + (lo & 1);
        if (fe <= hi) rl[nr++] = rp;
    }
#pragma unroll
    for (int dc = -2; dc <= 2; ++dc) {
        int cp = c + dc;
        if (cp < 0 || cp > 31) continue;
        int lo = (c > cp ? c : cp) - 1; if (lo < 0) lo = 0;
        int hi = (c < cp ? c : cp) + 1; if (hi > 30) hi = 30;
        int fe = lo + (lo & 1);
        if (fe <= hi) cl[nc++] = cp;
    }
    int cnt = 1 + nr * nc;
    g_kcnt[t] = cnt;
    for (int j = 0; j < 32; ++j) {
        int key = 0;
        if (j >= 1 && j < cnt) {
            int i = j - 1;
            key = rl[i / nc] * 32 + cl[i % nc] + 1;
        }
        g_keys[t * 32 + j] = key * (3 * C_);
    }
}

// ---------------------------------------------------------------------------
// LayerNorm; rows >= inRows emit zeros (pad fusion); roundMain rounds the
// main output to tf32; outR = extra rounded copy.
// ---------------------------------------------------------------------------
__global__ void ln_kernel(const float* __restrict__ in, float* __restrict__ out,
                          const float* __restrict__ gw, const float* __restrict__ gb,
                          int inStride, int outStride, int inRows, int roundMain,
                          float* __restrict__ outR) {
    int i = blockIdx.x, b = blockIdx.y;
    int tid = threadIdx.x;
    float* yr = out + ((size_t)b * outStride + i) * C_;
    if (i >= inRows) {
        yr[tid] = 0.f; yr[tid + 128] = 0.f; yr[tid + 256] = 0.f;
        if (outR) {
            float* zr = outR + ((size_t)b * outStride + i) * C_;
            zr[tid] = 0.f; zr[tid + 128] = 0.f; zr[tid + 256] = 0.f;
        }
        return;
    }
    const float* xr = in + ((size_t)b * inStride + i) * C_;
    float v0 = xr[tid], v1 = xr[tid + 128], v2 = xr[tid + 256];
    __shared__ float sm[4];
    float s = warpSum(v0 + v1 + v2);
    if ((tid & 31) == 0) sm[tid >> 5] = s;
    __syncthreads();
    float mu = (sm[0] + sm[1] + sm[2] + sm[3]) * (1.f / 384.f);
    float d0 = v0 - mu, d1 = v1 - mu, d2 = v2 - mu;
    __syncthreads();
    float q = warpSum(d0 * d0 + d1 * d1 + d2 * d2);
    if ((tid & 31) == 0) sm[tid >> 5] = q;
    __syncthreads();
    float var = (sm[0] + sm[1] + sm[2] + sm[3]) * (1.f / 384.f);
    float rs = rsqrtf(var + 1e-5f);
    float r0 = d0 * rs * gw[tid]       + gb[tid];
    float r1 = d1 * rs * gw[tid + 128] + gb[tid + 128];
    float r2 = d2 * rs * gw[tid + 256] + gb[tid + 256];
    if (roundMain) { r0 = rtf(r0); r1 = rtf(r1); r2 = rtf(r2); }
    yr[tid]       = r0;
    yr[tid + 128] = r1;
    yr[tid + 256] = r2;
    if (outR) {
        float* zr = outR + ((size_t)b * outStride + i) * C_;
        zr[tid]       = rtf(r0);
        zr[tid + 128] = rtf(r1);
        zr[tid + 256] = rtf(r2);
    }
}

// ---------------------------------------------------------------------------
// TF32 tensor-core GEMM: 128x64x32, 256 threads, 2-stage cp.async,
// ldmatrix.x4 fragment loads, CVT-free mainloop (inputs pre-rounded).
// GATHER: pool A-path gather. CATMODE: output row remap row+row/256+1.
// roundOut rounds stored values.
// ---------------------------------------------------------------------------
#define KP_ 36
#define TG_SMEM ((2*128*KP_ + 2*64*KP_) * 4)   // 55296 bytes
#define SA_STAGE_BYTES (128*KP_*4)
#define SB_STAGE_BYTES (64*KP_*4)
#define SB_BASE_BYTES  (2*128*KP_*4)

template<int GATHER, int CATMODE>
__global__ void __launch_bounds__(256)
tgemm_kernel(int M, int N, int K,
             const float* __restrict__ A, const float* __restrict__ Wt,
             const float* __restrict__ bias, const float* __restrict__ resid,
             float* __restrict__ Cc, int doGelu, int roundOut) {
    extern __shared__ float dyn[];
    float (*sA)[128][KP_] = (float(*)[128][KP_])dyn;
    float (*sB)[64][KP_]  = (float(*)[64][KP_])(dyn + 2 * 128 * KP_);

    int tid  = threadIdx.x;
    int lane = tid & 31;
    int wid  = tid >> 5;
    int wm   = wid & 3;
    int wn   = wid >> 2;
    int lr   = lane >> 2;
    int lc   = lane & 3;

    int bm = blockIdx.y * 128;
    int bn = blockIdx.x * 64;

    int ldRow = tid >> 3;
    int ldC4  = tid & 7;

    unsigned smemU = (unsigned)__cvta_generic_to_shared(dyn);
    int lm = lane >> 3;
    int lrr = lane & 7;
    unsigned aAddr[2];
#pragma unroll
    for (int mt = 0; mt < 2; ++mt)
        aAddr[mt] = smemU +
            ((unsigned)((wm * 32 + mt * 16 + (lm & 1) * 8 + lrr) * KP_ + (lm >> 1) * 4)) * 4u;
    unsigned bAddr = smemU + SB_BASE_BYTES +
        ((unsigned)((wn * 32 + lm * 8 + lrr) * KP_)) * 4u;

    float acc[2][4][4];
#pragma unroll
    for (int mt = 0; mt < 2; ++mt)
#pragma unroll
        for (int nt = 0; nt < 4; ++nt)
#pragma unroll
            for (int e = 0; e < 4; ++e) acc[mt][nt][e] = 0.f;

    int nIter = K >> 5;

    auto loadTile = [&](int it, int s) {
        int k0 = it << 5;
        if (!GATHER) {
#pragma unroll
            for (int i = 0; i < 4; ++i) {
                int r = ldRow + i * 32;
                int gr = bm + r;
                bool p = gr < M;
                const float* src = A + (size_t)(p ? gr : 0) * K + k0 + ldC4 * 4;
                cpasync16(&sA[s][r][ldC4 * 4], src, p);
            }
        } else {
            int kk = k0 / 384;
            int c0 = k0 - kk * 384;
#pragma unroll
            for (int i = 0; i < 4; ++i) {
                int r = ldRow + i * 32;
                int gr = bm + r;
                int b = gr >> 8, w = gr & 255;
                int wi = w >> 4, wj = w & 15;
                int rr = 2 * wi + kk / 3 - 1;
                int cc = 2 * wj + kk % 3 - 1;
                int hrow = (rr < 0 || cc < 0) ? 1024 : rr * 32 + cc + 1;
                const float* src = A + ((size_t)b * 1025 + hrow) * 384 + c0 + ldC4 * 4;
                cpasync16(&sA[s][r][ldC4 * 4], src, true);
            }
        }
#pragma unroll
        for (int i = 0; i < 2; ++i) {
            int n = ldRow + i * 32;
            int gn = bn + n;
            bool p = gn < N;
            const float* src = Wt + (size_t)(p ? gn : 0) * K + k0 + ldC4 * 4;
            cpasync16(&sB[s][n][ldC4 * 4], src, p);
        }
    };

    loadTile(0, 0);
    asm volatile("cp.async.commit_group;\n");

    for (int it = 0; it < nIter; ++it) {
        int s = it & 1;
        if (it + 1 < nIter) {
            loadTile(it + 1, s ^ 1);
            asm volatile("cp.async.commit_group;\n");
            asm volatile("cp.async.wait_group 1;\n");
        } else {
            asm volatile("cp.async.wait_group 0;\n");
        }
        __syncthreads();

        unsigned sAoff = (unsigned)(s * SA_STAGE_BYTES);
        unsigned sBoff = (unsigned)(s * SB_STAGE_BYTES);

#pragma unroll
        for (int ks = 0; ks < 4; ++ks) {
            unsigned kOff = (unsigned)(ks * 8 * 4);
            unsigned a[2][4], bf[4][2];
#pragma unroll
            for (int mt = 0; mt < 2; ++mt)
                ldsm4(a[mt][0], a[mt][1], a[mt][2], a[mt][3],
                      aAddr[mt] + sAoff + kOff);
            {
                unsigned b0, b1, b2, b3;
                ldsm4(b0, b1, b2, b3, bAddr + sBoff + kOff);
                bf[0][0] = b0; bf[1][0] = b1; bf[2][0] = b2; bf[3][0] = b3;
                ldsm4(b0, b1, b2, b3, bAddr + sBoff + kOff + 16);
                bf[0][1] = b0; bf[1][1] = b1; bf[2][1] = b2; bf[3][1] = b3;
            }
#pragma unroll
            for (int mt = 0; mt < 2; ++mt)
#pragma unroll
                for (int nt = 0; nt < 4; ++nt) {
                    asm volatile(
                        "mma.sync.aligned.m16n8k8.row.col.f32.tf32.tf32.f32 "
                        "{%0,%1,%2,%3}, {%4,%5,%6,%7}, {%8,%9}, {%0,%1,%2,%3};\n"
                        : "+f"(acc[mt][nt][0]), "+f"(acc[mt][nt][1]),
                          "+f"(acc[mt][nt][2]), "+f"(acc[mt][nt][3])
                        : "r"(a[mt][0]), "r"(a[mt][1]), "r"(a[mt][2]), "r"(a[mt][3]),
                          "r"(bf[nt][0]), "r"(bf[nt][1]));
                }
        }
        __syncthreads();
    }

#pragma unroll
    for (int mt = 0; mt < 2; ++mt) {
#pragma unroll
        for (int nt = 0; nt < 4; ++nt) {
            int col = bn + wn * 32 + nt * 8 + 2 * lc;
            float bx = 0.f, by = 0.f;
            if (bias) { bx = bias[col]; by = bias[col + 1]; }
#pragma unroll
            for (int half = 0; half < 2; ++half) {
                int row = bm + wm * 32 + mt * 16 + lr + half * 8;
                if (row >= M) continue;
                float vx = acc[mt][nt][2 * half + 0] + bx;
                float vy = acc[mt][nt][2 * half + 1] + by;
                if (resid) {
                    const float2 rv = *(const float2*)(resid + (size_t)row * N + col);
                    vx += rv.x; vy += rv.y;
                }
                if (doGelu) {
                    vx = 0.5f * vx * (1.f + erff(vx * 0.70710678118654752f));
                    vy = 0.5f * vy * (1.f + erff(vy * 0.70710678118654752f));
                }
                if (roundOut) { vx = rtf(vx); vy = rtf(vy); }
                int orow = CATMODE ? (row + (row >> 8) + 1) : row;
                *(float2*)(Cc + (size_t)orow * N + col) = make_float2(vx, vy);
            }
        }
    }
}

// ---------------------------------------------------------------------------
// Sparse attention (token queries); outputs rounded for the proj GEMM.
// ---------------------------------------------------------------------------
__global__ void attn_token_kernel() {
    int gw = (blockIdx.x * blockDim.x + threadIdx.x) >> 5;
    int lane = threadIdx.x & 31;
    int t  = gw & 1023;
    int bh = gw >> 10;
    int h = bh % H_;
    int b = bh / H_;

    int key_off = g_keys[t * 32 + lane];
    int cnt     = g_kcnt[t];

    const float* qp = g_qkv + ((size_t)b * M_ + (t + 1)) * (3 * C_) + h * D_;
    int hl = lane & 15;
    float4 qv = *(const float4*)(qp + hl * 4);
    const float* kbase = g_qkv + (size_t)b * M_ * (3 * C_) + C_ + h * D_;

    float s = -INFINITY;
    for (int j0 = 0; j0 < 26; j0 += 2) {
        if (j0 >= cnt) break;
        int ka = __shfl_sync(0xffffffffu, key_off, j0);
        int kb = __shfl_sync(0xffffffffu, key_off, j0 + 1);
        int kidx = (lane < 16) ? ka : kb;
        float4 kv = *(const float4*)(kbase + kidx + hl * 4);
        float d = qv.x * kv.x + qv.y * kv.y + qv.z * kv.z + qv.w * kv.w;
        d += __shfl_xor_sync(0xffffffffu, d, 8);
        d += __shfl_xor_sync(0xffffffffu, d, 4);
        d += __shfl_xor_sync(0xffffffffu, d, 2);
        d += __shfl_xor_sync(0xffffffffu, d, 1);
        float dx = __shfl_xor_sync(0xffffffffu, d, 16);
        float da = (lane < 16) ? d : dx;
        float db = (lane < 16) ? dx : d;
        if (lane == j0)     s = da * SCALE_;
        if (lane == j0 + 1) s = db * SCALE_;
    }
    if (lane >= cnt) s = -INFINITY;

    float m = fmaxf(warpMax(s), 0.f);
    float p = (lane < cnt) ? expf(s - m) : 0.f;
    float denom = warpSum(p) + expf(-m);
    float inv = 1.f / denom;

    const float* vbase = g_qkv + (size_t)b * M_ * (3 * C_) + 2 * C_ + h * D_;
    float o0 = 0.f, o1 = 0.f;
    for (int j = 0; j < cnt; ++j) {
        float pj = __shfl_sync(0xffffffffu, p, j);
        int   kj = __shfl_sync(0xffffffffu, key_off, j);
        float2 vv = *(const float2*)(vbase + kj + 2 * lane);
        o0 += pj * vv.x;
        o1 += pj * vv.y;
    }
    float* op = g_att + ((size_t)b * M_ + (t + 1)) * C_ + h * D_;
    *(float2*)(op + 2 * lane) = make_float2(rtf(o0 * inv), rtf(o1 * inv));
}

// ---------------------------------------------------------------------------
// CLS attention, split-K.
// ---------------------------------------------------------------------------
__global__ void attn_cls_part_kernel() {
    int chunk = blockIdx.x;
    int bh    = blockIdx.y;
    int b = bh / H_, h = bh % H_;
    int start = chunk * 129;
    int end   = start + 129; if (end > 1025) end = 1025;
    int cnt   = end - start;
    int tid = threadIdx.x;

    __shared__ float sq[64];
    __shared__ float sc[132];
    __shared__ float sred[4];
    __shared__ float oacc[128];

    const float* qp = g_qkv + (size_t)(b * M_) * (3 * C_) + h * D_;
    if (tid < 64) sq[tid] = qp[tid];
    __syncthreads();

    for (int j = tid; j < cnt; j += 128) {
        const float* kp = g_qkv + ((size_t)b * M_ + start + j) * (3 * C_) + C_ + h * D_;
        float acc = 0.f;
#pragma unroll
        for (int d0 = 0; d0 < D_; d0 += 4) {
            float4 kv = *(const float4*)(kp + d0);
            acc += sq[d0] * kv.x + sq[d0 + 1] * kv.y + sq[d0 + 2] * kv.z + sq[d0 + 3] * kv.w;
        }
        sc[j] = acc * SCALE_;
    }
    __syncthreads();

    float m = -INFINITY;
    for (int j = tid; j < cnt; j += 128) m = fmaxf(m, sc[j]);
    m = warpMax(m);
    if ((tid & 31) == 0) sred[tid >> 5] = m;
    __syncthreads();
    m = fmaxf(fmaxf(sred[0], sred[1]), fmaxf(sred[2], sred[3]));
    __syncthreads();

    float ls = 0.f;
    for (int j = tid; j < cnt; j += 128) {
        float pv = expf(sc[j] - m);
        sc[j] = pv;
        ls += pv;
    }
    ls = warpSum(ls);
    if ((tid & 31) == 0) sred[tid >> 5] = ls;
    __syncthreads();
    float ssum = sred[0] + sred[1] + sred[2] + sred[3];

    int d = tid & 63, grp = tid >> 6;
    float acc = 0.f;
    for (int j = grp; j < cnt; j += 2)
        acc += sc[j] * g_qkv[((size_t)b * M_ + start + j) * (3 * C_) + 2 * C_ + h * D_ + d];
    oacc[tid] = acc;
    __syncthreads();

    float* dst = g_clsp + ((size_t)bh * 8 + chunk) * 66;
    if (tid < 64) dst[2 + tid] = oacc[tid] + oacc[tid + 64];
    if (tid == 0) { dst[0] = m; dst[1] = ssum; }
}

__global__ void attn_cls_comb_kernel() {
    int bh = blockIdx.x;
    int b = bh / H_, h = bh % H_;
    int d = threadIdx.x;
    const float* src = g_clsp + (size_t)bh * 8 * 66;
    float M = 0.f;
#pragma unroll
    for (int c = 0; c < 8; ++c) M = fmaxf(M, src[c * 66]);
    float denom = expf(-M);
    float o = 0.f;
#pragma unroll
    for (int c = 0; c < 8; ++c) {
        float w = expf(src[c * 66] - M);
        denom += src[c * 66 + 1] * w;
        o += src[c * 66 + 2 + d] * w;
    }
    g_att[(size_t)(b * M_) * C_ + h * D_ + d] = rtf(o / denom);
}

// Pad query.
__global__ void attn_pad_kernel() {
    int b = blockIdx.y;
    int cg = blockIdx.x;
    int tid = threadIdx.x;
    int cl = tid & 31;
    int rg = tid >> 5;
    int ch = cg * 32 + cl;
    const float* base = g_qkv + (size_t)b * M_ * (3 * C_) + 2 * C_ + ch;
    float acc = 0.f;
    for (int mrow = rg; mrow < 1025; mrow += 8)
        acc += base[(size_t)mrow * (3 * C_)];
    __shared__ float sm2[8][32];
    sm2[rg][cl] = acc;
    __syncthreads();
    if (tid < 32) {
        float a = 0.f;
#pragma unroll
        for (int rr = 0; rr < 8; ++rr) a += sm2[rr][tid];
        g_att[((size_t)b * M_ + 1025) * C_ + cg * 32 + tid] = rtf(a * (1.0f / 1026.0f));
    }
}

// Copy LN2 row 0 (CLS) into g_cat row 0 of each batch (float4: 96 threads).
__global__ void cls_copy_kernel() {
    int b = blockIdx.x;
    int t = threadIdx.x;
    ((float4*)(g_cat + (size_t)b * CAT_ * C_))[t] =
        ((const float4*)(g_h2 + (size_t)b * 1025 * C_))[t];
}

// ---------------------------------------------------------------------------
// Launch
// ---------------------------------------------------------------------------
extern "C" void kernel_launch(void* const* d_in, const int* in_sizes, int n_in,
                              void* d_out, int out_size) {
    const float* x      = (const float*)d_in[0];
    const float* n1w    = (const float*)d_in[1];
    const float* n1b    = (const float*)d_in[2];
    const float* qkv_w  = (const float*)d_in[3];
    const float* proj_w = (const float*)d_in[4];
    const float* proj_b = (const float*)d_in[5];
    const float* n2w    = (const float*)d_in[6];
    const float* n2b    = (const float*)d_in[7];
    const float* pool_w = (const float*)d_in[8];
    const float* pool_b = (const float*)d_in[9];
    const float* n3w    = (const float*)d_in[10];
    const float* n3b    = (const float*)d_in[11];
    const float* fc1_w  = (const float*)d_in[12];
    const float* fc1_b  = (const float*)d_in[13];
    const float* fc2_w  = (const float*)d_in[14];
    const float* fc2_b  = (const float*)d_in[15];
    float* out = (float*)d_out;

    float *h1, *h1r, *qkvp, *att, *res, *h2, *cat, *h3, *fc1o;
    float *wqkv, *wproj, *wpool, *wfc1, *wfc2;
    cudaGetSymbolAddress((void**)&h1,    g_h1);
    cudaGetSymbolAddress((void**)&h1r,   g_h1r);
    cudaGetSymbolAddress((void**)&qkvp,  g_qkv);
    cudaGetSymbolAddress((void**)&att,   g_att);
    cudaGetSymbolAddress((void**)&res,   g_res);
    cudaGetSymbolAddress((void**)&h2,    g_h2);
    cudaGetSymbolAddress((void**)&cat,   g_cat);
    cudaGetSymbolAddress((void**)&h3,    g_h3);
    cudaGetSymbolAddress((void**)&fc1o,  g_fc1);
    cudaGetSymbolAddress((void**)&wqkv,  g_wqkv);
    cudaGetSymbolAddress((void**)&wproj, g_wproj);
    cudaGetSymbolAddress((void**)&wpool, g_wpool);
    cudaGetSymbolAddress((void**)&wfc1,  g_wfc1);
    cudaGetSymbolAddress((void**)&wfc2,  g_wfc2);

    static int smemSet = 0;
    if (!smemSet) {
        cudaFuncSetAttribute((const void*)&tgemm_kernel<0,0>,
                             cudaFuncAttributeMaxDynamicSharedMemorySize, TG_SMEM);
        cudaFuncSetAttribute((const void*)&tgemm_kernel<1,1>,
                             cudaFuncAttributeMaxDynamicSharedMemorySize, TG_SMEM);
        smemSet = 1;
    }

    const int MROWS = B_ * M_;        // 8208
    const int PROWS = B_ * W_;        // 2048
    const int CROWS = B_ * CAT_;      // 2056

    // prep: weights rounding + key table, one launch
    prep_kernel<<<WB_ + 4, 256>>>(
        (const float4*)qkv_w, (const float4*)proj_w, (const float4*)pool_w,
        (const float4*)fc1_w, (const float4*)fc2_w);

    // LN1: exact -> h1, rounded -> h1r; row 1025 zeroed in both (pad fusion)
    ln_kernel<<<dim3(1026, B_), 128>>>(x, h1, n1w, n1b, 1025, M_, 1025, 0, h1r);

    tgemm_kernel<0,0><<<dim3(1152 / 64, (MROWS + 127) / 128), 256, TG_SMEM>>>(
        MROWS, 3 * C_, C_, h1r, wqkv, nullptr, nullptr, qkvp, 0, 0);

    attn_token_kernel<<<(B_ * H_ * NT_) / 8, 256>>>();
    attn_cls_part_kernel<<<dim3(8, B_ * H_), 128>>>();
    attn_cls_comb_kernel<<<B_ * H_, 64>>>();
    attn_pad_kernel<<<dim3(12, B_), 256>>>();

    tgemm_kernel<0,0><<<dim3(C_ / 64, (MROWS + 127) / 128), 256, TG_SMEM>>>(
        MROWS, C_, C_, att, wproj, proj_b, h1, res, 0, 0);

    // LN2 output rounded (pool GEMM A)
    ln_kernel<<<dim3(1025, B_), 128>>>(res, h2, n2w, n2b, M_, 1025, 1025, 1, nullptr);

    // pool GEMM with fused gather, writes directly into g_cat rows 1..256
    tgemm_kernel<1,1><<<dim3(C_ / 64, PROWS / 128), 256, TG_SMEM>>>(
        PROWS, C_, 9 * C_, h2, wpool, pool_b, nullptr, cat, 0, 0);
    cls_copy_kernel<<<B_, 96>>>();

    // LN3 output rounded (fc1 GEMM A)
    ln_kernel<<<dim3(CAT_, B_), 128>>>(cat, h3, n3w, n3b, CAT_, CAT_, CAT_, 1, nullptr);

    tgemm_kernel<0,0><<<dim3(HID_ / 64, (CROWS + 127) / 128), 256, TG_SMEM>>>(
        CROWS, HID_, C_, h3, wfc1, fc1_b, nullptr, fc1o, 1, 1);
    tgemm_kernel<0,0><<<dim3(C_ / 64, (CROWS + 127) / 128), 256, TG_SMEM>>>(
        CROWS, C_, HID_, fc1o, wfc2, fc2_b, nullptr, out, 0, 0);
}

// round 16
// speedup vs baseline: 1.2732x; 1.0092x over previous
#include <cuda_runtime.h>
#include <math.h>

#define B_    8
#define M_    1026
#define NT_   1024
#define C_    384
#define H_    6
#define D_    64
#define HID_  1536
#define W_    256
#define CAT_  257
#define SCALE_ 0.4082482904638631f

// ---------------------------------------------------------------------------
// Scratch
// ---------------------------------------------------------------------------
__device__ float g_h1  [B_*M_*C_];        // LN1 exact (proj residual)
__device__ float g_h1r [B_*M_*C_];        // LN1 tf32-rounded (QKV GEMM A)
__device__ float g_qkv [B_*M_*3*C_];
__device__ float g_att [B_*M_*C_];        // tf32-rounded at write
__device__ float g_res [B_*M_*C_];
__device__ float g_h2  [B_*(NT_+1)*C_];   // tf32-rounded (pool GEMM A)
__device__ float g_cat [B_*CAT_*C_];
__device__ float g_h3  [B_*CAT_*C_];      // tf32-rounded (fc1 GEMM A)
__device__ float g_fc1 [B_*CAT_*HID_];    // tf32-rounded (fc2 GEMM A)
__device__ float g_clsp[48*8*66];
// pre-rounded weights
__device__ float g_wqkv [3*C_*C_];
__device__ float g_wproj[C_*C_];
__device__ float g_wpool[C_*9*C_];
__device__ float g_wfc1 [HID_*C_];
__device__ float g_wfc2 [C_*HID_];
// precomputed sparse-attention key table
__device__ int   g_keys[NT_*32];
__device__ int   g_kcnt[NT_];

// ---------------------------------------------------------------------------
// Helpers
// ---------------------------------------------------------------------------
__device__ __forceinline__ float warpSum(float v) {
#pragma unroll
    for (int o = 16; o > 0; o >>= 1) v += __shfl_xor_sync(0xffffffffu, v, o);
    return v;
}
__device__ __forceinline__ float warpMax(float v) {
#pragma unroll
    for (int o = 16; o > 0; o >>= 1) v = fmaxf(v, __shfl_xor_sync(0xffffffffu, v, o));
    return v;
}
__device__ __forceinline__ unsigned f2tf(float f) {
    unsigned u;
    asm("cvt.rna.tf32.f32 %0, %1;" : "=r"(u) : "f"(f));
    return u;
}
__device__ __forceinline__ float rtf(float f) { return __uint_as_float(f2tf(f)); }
__device__ __forceinline__ void cpasync16(void* smem_dst, const void* gsrc, bool pred) {
    unsigned saddr = (unsigned)__cvta_generic_to_shared(smem_dst);
    int sz = pred ? 16 : 0;
    asm volatile("cp.async.ca.shared.global [%0], [%1], 16, %2;\n"
                 :: "r"(saddr), "l"(gsrc), "r"(sz));
}
__device__ __forceinline__ void ldsm4(unsigned& r0, unsigned& r1, unsigned& r2, unsigned& r3,
                                      unsigned addr) {
    asm volatile("ldmatrix.sync.aligned.m8n8.x4.shared.b16 {%0,%1,%2,%3}, [%4];\n"
                 : "=r"(r0), "=r"(r1), "=r"(r2), "=r"(r3) : "r"(addr));
}

// ---------------------------------------------------------------------------
// Merged prep: weight rounding (blocks 0..WB-1) + key table (last 4 blocks).
// ---------------------------------------------------------------------------
#define WQ4 110592
#define WP4 36864
#define WO4 331776
#define W14 147456
#define W24 147456
#define WT4 (WQ4+WP4+WO4+W14+W24)   // 774144
#define WB_ ((WT4 + 255) / 256)     // 3024

__global__ void prep_kernel(const float4* __restrict__ qkv,
                            const float4* __restrict__ proj,
                            const float4* __restrict__ pool,
                            const float4* __restrict__ f1,
                            const float4* __restrict__ f2) {
    int blk = blockIdx.x;
    int tid = threadIdx.x;
    if (blk < WB_) {
        int i = blk * 256 + tid;
        if (i >= WT4) return;
        const float4* src;
        float4* dst;
        int o = i;
        if (o < WQ4)               { src = qkv  + o; dst = (float4*)g_wqkv  + o; }
        else if ((o -= WQ4) < WP4) { src = proj + o; dst = (float4*)g_wproj + o; }
        else if ((o -= WP4) < WO4) { src = pool + o; dst = (float4*)g_wpool + o; }
        else if ((o -= WO4) < W14) { src = f1   + o; dst = (float4*)g_wfc1  + o; }
        else { o -= W14;             src = f2   + o; dst = (float4*)g_wfc2  + o; }
        float4 v = *src;
        *dst = make_float4(rtf(v.x), rtf(v.y), rtf(v.z), rtf(v.w));
        return;
    }
    // key-table blocks: t in [0, 1024)
    int t = (blk - WB_) * 256 + tid;
    int r = t >> 5, c = t & 31;
    int rl[5], cl[5];
    int nr = 0, nc = 0;
#pragma unroll
    for (int dr = -2; dr <= 2; ++dr) {
        int rp = r + dr;
        if (rp < 0 || rp > 31) continue;
        int lo = (r > rp ? r : rp) - 1; if (lo < 0) lo = 0;
        int hi = (r < rp ? r : rp) + 1; if (hi > 30) hi = 30;
        int fe = lo + (lo & 1);
        if (fe <= hi) rl[nr++] = rp;
    }
#pragma unroll
    for (int dc = -2; dc <= 2; ++dc) {
        int cp = c + dc;
        if (cp < 0 || cp > 31) continue;
        int lo = (c > cp ? c : cp) - 1; if (lo < 0) lo = 0;
        int hi = (c < cp ? c : cp) + 1; if (hi > 30) hi = 30;
        int fe = lo + (lo & 1);
        if (fe <= hi) cl[nc++] = cp;
    }
    int cnt = 1 + nr * nc;
    g_kcnt[t] = cnt;
    for (int j = 0; j < 32; ++j) {
        int key = 0;
        if (j >= 1 && j < cnt) {
            int i = j - 1;
            key = rl[i / nc] * 32 + cl[i % nc] + 1;
        }
        g_keys[t * 32 + j] = key * (3 * C_);
    }
}

// ---------------------------------------------------------------------------
// LayerNorm; rows >= inRows emit zeros; roundMain rounds; outR = rounded copy
// ---------------------------------------------------------------------------
__global__ void ln_kernel(const float* __restrict__ in, float* __restrict__ out,
                          const float* __restrict__ gw, const float* __restrict__ gb,
                          int inStride, int outStride, int inRows, int roundMain,
                          float* __restrict__ outR) {
    int i = blockIdx.x, b = blockIdx.y;
    int tid = threadIdx.x;
    float* yr = out + ((size_t)b * outStride + i) * C_;
    if (i >= inRows) {
        yr[tid] = 0.f; yr[tid + 128] = 0.f; yr[tid + 256] = 0.f;
        if (outR) {
            float* zr = outR + ((size_t)b * outStride + i) * C_;
            zr[tid] = 0.f; zr[tid + 128] = 0.f; zr[tid + 256] = 0.f;
        }
        return;
    }
    const float* xr = in + ((size_t)b * inStride + i) * C_;
    float v0 = xr[tid], v1 = xr[tid + 128], v2 = xr[tid + 256];
    __shared__ float sm[4];
    float s = warpSum(v0 + v1 + v2);
    if ((tid & 31) == 0) sm[tid >> 5] = s;
    __syncthreads();
    float mu = (sm[0] + sm[1] + sm[2] + sm[3]) * (1.f / 384.f);
    float d0 = v0 - mu, d1 = v1 - mu, d2 = v2 - mu;
    __syncthreads();
    float q = warpSum(d0 * d0 + d1 * d1 + d2 * d2);
    if ((tid & 31) == 0) sm[tid >> 5] = q;
    __syncthreads();
    float var = (sm[0] + sm[1] + sm[2] + sm[3]) * (1.f / 384.f);
    float rs = rsqrtf(var + 1e-5f);
    float r0 = d0 * rs * gw[tid]       + gb[tid];
    float r1 = d1 * rs * gw[tid + 128] + gb[tid + 128];
    float r2 = d2 * rs * gw[tid + 256] + gb[tid + 256];
    if (roundMain) { r0 = rtf(r0); r1 = rtf(r1); r2 = rtf(r2); }
    yr[tid]       = r0;
    yr[tid + 128] = r1;
    yr[tid + 256] = r2;
    if (outR) {
        float* zr = outR + ((size_t)b * outStride + i) * C_;
        zr[tid]       = rtf(r0);
        zr[tid + 128] = rtf(r1);
        zr[tid + 256] = rtf(r2);
    }
}

// ---------------------------------------------------------------------------
// TF32 tensor-core GEMM: 128x64x32, 256 threads, 2-stage cp.async,
// ldmatrix.x4, cvt-free mainloop. GATHER = pool A gather.
// CATMODE = output row remap row+row/256+1. roundOut rounds stores.
// ---------------------------------------------------------------------------
#define KP_ 36
#define TG_SMEM ((2*128*KP_ + 2*64*KP_) * 4)   // 55296 bytes
#define SA_STAGE_BYTES (128*KP_*4)
#define SB_STAGE_BYTES (64*KP_*4)
#define SB_BASE_BYTES  (2*128*KP_*4)

template<int GATHER, int CATMODE>
__global__ void __launch_bounds__(256)
tgemm_kernel(int M, int N, int K,
             const float* __restrict__ A, const float* __restrict__ Wt,
             const float* __restrict__ bias, const float* __restrict__ resid,
             float* __restrict__ Cc, int doGelu, int roundOut) {
    extern __shared__ float dyn[];
    float (*sA)[128][KP_] = (float(*)[128][KP_])dyn;
    float (*sB)[64][KP_]  = (float(*)[64][KP_])(dyn + 2 * 128 * KP_);

    int tid  = threadIdx.x;
    int lane = tid & 31;
    int wid  = tid >> 5;
    int wm   = wid & 3;
    int wn   = wid >> 2;
    int lr   = lane >> 2;
    int lc   = lane & 3;

    int bm = blockIdx.y * 128;
    int bn = blockIdx.x * 64;

    int ldRow = tid >> 3;
    int ldC4  = tid & 7;

    unsigned smemU = (unsigned)__cvta_generic_to_shared(dyn);
    int lm = lane >> 3;
    int lrr = lane & 7;
    unsigned aAddr[2];
#pragma unroll
    for (int mt = 0; mt < 2; ++mt)
        aAddr[mt] = smemU +
            ((unsigned)((wm * 32 + mt * 16 + (lm & 1) * 8 + lrr) * KP_ + (lm >> 1) * 4)) * 4u;
    unsigned bAddr = smemU + SB_BASE_BYTES +
        ((unsigned)((wn * 32 + lm * 8 + lrr) * KP_)) * 4u;

    float acc[2][4][4];
#pragma unroll
    for (int mt = 0; mt < 2; ++mt)
#pragma unroll
        for (int nt = 0; nt < 4; ++nt)
#pragma unroll
            for (int e = 0; e < 4; ++e) acc[mt][nt][e] = 0.f;

    int nIter = K >> 5;

    auto loadTile = [&](int it, int s) {
        int k0 = it << 5;
        if (!GATHER) {
#pragma unroll
            for (int i = 0; i < 4; ++i) {
                int r = ldRow + i * 32;
                int gr = bm + r;
                bool p = gr < M;
                const float* src = A + (size_t)(p ? gr : 0) * K + k0 + ldC4 * 4;
                cpasync16(&sA[s][r][ldC4 * 4], src, p);
            }
        } else {
            int kk = k0 / 384;
            int c0 = k0 - kk * 384;
#pragma unroll
            for (int i = 0; i < 4; ++i) {
                int r = ldRow + i * 32;
                int gr = bm + r;
                int b = gr >> 8, w = gr & 255;
                int wi = w >> 4, wj = w & 15;
                int rr = 2 * wi + kk / 3 - 1;
                int cc = 2 * wj + kk % 3 - 1;
                int hrow = (rr < 0 || cc < 0) ? 1024 : rr * 32 + cc + 1;
                const float* src = A + ((size_t)b * 1025 + hrow) * 384 + c0 + ldC4 * 4;
                cpasync16(&sA[s][r][ldC4 * 4], src, true);
            }
        }
#pragma unroll
        for (int i = 0; i < 2; ++i) {
            int n = ldRow + i * 32;
            int gn = bn + n;
            bool p = gn < N;
            const float* src = Wt + (size_t)(p ? gn : 0) * K + k0 + ldC4 * 4;
            cpasync16(&sB[s][n][ldC4 * 4], src, p);
        }
    };

    loadTile(0, 0);
    asm volatile("cp.async.commit_group;\n");

    for (int it = 0; it < nIter; ++it) {
        int s = it & 1;
        if (it + 1 < nIter) {
            loadTile(it + 1, s ^ 1);
            asm volatile("cp.async.commit_group;\n");
            asm volatile("cp.async.wait_group 1;\n");
        } else {
            asm volatile("cp.async.wait_group 0;\n");
        }
        __syncthreads();

        unsigned sAoff = (unsigned)(s * SA_STAGE_BYTES);
        unsigned sBoff = (unsigned)(s * SB_STAGE_BYTES);

#pragma unroll
        for (int ks = 0; ks < 4; ++ks) {
            unsigned kOff = (unsigned)(ks * 8 * 4);
            unsigned a[2][4], bf[4][2];
#pragma unroll
            for (int mt = 0; mt < 2; ++mt)
                ldsm4(a[mt][0], a[mt][1], a[mt][2], a[mt][3],
                      aAddr[mt] + sAoff + kOff);
            {
                unsigned b0, b1, b2, b3;
                ldsm4(b0, b1, b2, b3, bAddr + sBoff + kOff);
                bf[0][0] = b0; bf[1][0] = b1; bf[2][0] = b2; bf[3][0] = b3;
                ldsm4(b0, b1, b2, b3, bAddr + sBoff + kOff + 16);
                bf[0][1] = b0; bf[1][1] = b1; bf[2][1] = b2; bf[3][1] = b3;
            }
#pragma unroll
            for (int mt = 0; mt < 2; ++mt)
#pragma unroll
                for (int nt = 0; nt < 4; ++nt) {
                    asm volatile(
                        "mma.sync.aligned.m16n8k8.row.col.f32.tf32.tf32.f32 "
                        "{%0,%1,%2,%3}, {%4,%5,%6,%7}, {%8,%9}, {%0,%1,%2,%3};\n"
                        : "+f"(acc[mt][nt][0]), "+f"(acc[mt][nt][1]),
                          "+f"(acc[mt][nt][2]), "+f"(acc[mt][nt][3])
                        : "r"(a[mt][0]), "r"(a[mt][1]), "r"(a[mt][2]), "r"(a[mt][3]),
                          "r"(bf[nt][0]), "r"(bf[nt][1]));
                }
        }
        __syncthreads();
    }

#pragma unroll
    for (int mt = 0; mt < 2; ++mt) {
#pragma unroll
        for (int nt = 0; nt < 4; ++nt) {
            int col = bn + wn * 32 + nt * 8 + 2 * lc;
            float bx = 0.f, by = 0.f;
            if (bias) { bx = bias[col]; by = bias[col + 1]; }
#pragma unroll
            for (int half = 0; half < 2; ++half) {
                int row = bm + wm * 32 + mt * 16 + lr + half * 8;
                if (row >= M) continue;
                float vx = acc[mt][nt][2 * half + 0] + bx;
                float vy = acc[mt][nt][2 * half + 1] + by;
                if (resid) {
                    const float2 rv = *(const float2*)(resid + (size_t)row * N + col);
                    vx += rv.x; vy += rv.y;
                }
                if (doGelu) {
                    vx = 0.5f * vx * (1.f + erff(vx * 0.70710678118654752f));
                    vy = 0.5f * vy * (1.f + erff(vy * 0.70710678118654752f));
                }
                if (roundOut) { vx = rtf(vx); vy = rtf(vy); }
                int orow = CATMODE ? (row + (row >> 8) + 1) : row;
                *(float2*)(Cc + (size_t)orow * N + col) = make_float2(vx, vy);
            }
        }
    }
}

// ---------------------------------------------------------------------------
// Sparse attention (token queries): TWO heads (hp, hp+3) per warp.
// Key shuffles / address math shared across the head pair; halves grid and
// per-warp fixed overhead. Outputs rounded for the proj GEMM.
// ---------------------------------------------------------------------------
__global__ void attn_token_kernel() {
    int gw = (blockIdx.x * blockDim.x + threadIdx.x) >> 5;
    int lane = threadIdx.x & 31;
    int t  = gw & 1023;
    int bh = gw >> 10;          // 0..23
    int hp = bh % 3;            // heads hp and hp+3
    int b  = bh / 3;

    int key_off = g_keys[t * 32 + lane];
    int cnt     = g_kcnt[t];

    const float* base = g_qkv + (size_t)b * M_ * (3 * C_);
    const float* qp = base + (size_t)(t + 1) * (3 * C_) + hp * D_;
    int hl = lane & 15;
    float4 qv0 = *(const float4*)(qp + hl * 4);
    float4 qv1 = *(const float4*)(qp + 3 * D_ + hl * 4);   // head hp+3
    const float* kbase = base + C_ + hp * D_;

    float s0 = -INFINITY, s1 = -INFINITY;
    for (int j0 = 0; j0 < 26; j0 += 2) {
        if (j0 >= cnt) break;
        int ka = __shfl_sync(0xffffffffu, key_off, j0);
        int kb = __shfl_sync(0xffffffffu, key_off, j0 + 1);
        int kidx = (lane < 16) ? ka : kb;
        const float* kp = kbase + kidx + hl * 4;
        float4 kv0 = *(const float4*)(kp);
        float4 kv1 = *(const float4*)(kp + 3 * D_);
        float d0 = qv0.x * kv0.x + qv0.y * kv0.y + qv0.z * kv0.z + qv0.w * kv0.w;
        float d1 = qv1.x * kv1.x + qv1.y * kv1.y + qv1.z * kv1.z + qv1.w * kv1.w;
#pragma unroll
        for (int o = 8; o > 0; o >>= 1) {
            d0 += __shfl_xor_sync(0xffffffffu, d0, o);
            d1 += __shfl_xor_sync(0xffffffffu, d1, o);
        }
        float dx0 = __shfl_xor_sync(0xffffffffu, d0, 16);
        float dx1 = __shfl_xor_sync(0xffffffffu, d1, 16);
        float da0 = (lane < 16) ? d0 : dx0;
        float db0 = (lane < 16) ? dx0 : d0;
        float da1 = (lane < 16) ? d1 : dx1;
        float db1 = (lane < 16) ? dx1 : d1;
        if (lane == j0)     { s0 = da0 * SCALE_; s1 = da1 * SCALE_; }
        if (lane == j0 + 1) { s0 = db0 * SCALE_; s1 = db1 * SCALE_; }
    }
    if (lane >= cnt) { s0 = -INFINITY; s1 = -INFINITY; }

    float m0 = fmaxf(warpMax(s0), 0.f);
    float m1 = fmaxf(warpMax(s1), 0.f);
    float p0 = (lane < cnt) ? expf(s0 - m0) : 0.f;
    float p1 = (lane < cnt) ? expf(s1 - m1) : 0.f;
    float inv0 = 1.f / (warpSum(p0) + expf(-m0));
    float inv1 = 1.f / (warpSum(p1) + expf(-m1));

    const float* vbase = base + 2 * C_ + hp * D_;
    float o00 = 0.f, o01 = 0.f, o10 = 0.f, o11 = 0.f;
    for (int j = 0; j < cnt; ++j) {
        float pj0 = __shfl_sync(0xffffffffu, p0, j);
        float pj1 = __shfl_sync(0xffffffffu, p1, j);
        int   kj  = __shfl_sync(0xffffffffu, key_off, j);
        const float* vp = vbase + kj + 2 * lane;
        float2 v0 = *(const float2*)(vp);
        float2 v1 = *(const float2*)(vp + 3 * D_);
        o00 += pj0 * v0.x; o01 += pj0 * v0.y;
        o10 += pj1 * v1.x; o11 += pj1 * v1.y;
    }
    float* op = g_att + ((size_t)b * M_ + (t + 1)) * C_ + hp * D_;
    *(float2*)(op + 2 * lane)          = make_float2(rtf(o00 * inv0), rtf(o01 * inv0));
    *(float2*)(op + 3 * D_ + 2 * lane) = make_float2(rtf(o10 * inv1), rtf(o11 * inv1));
}

// ---------------------------------------------------------------------------
// CLS attention, split-K.
// ---------------------------------------------------------------------------
__global__ void attn_cls_part_kernel() {
    int chunk = blockIdx.x;
    int bh    = blockIdx.y;
    int b = bh / H_, h = bh % H_;
    int start = chunk * 129;
    int end   = start + 129; if (end > 1025) end = 1025;
    int cnt   = end - start;
    int tid = threadIdx.x;

    __shared__ float sq[64];
    __shared__ float sc[132];
    __shared__ float sred[4];
    __shared__ float oacc[128];

    const float* qp = g_qkv + (size_t)(b * M_) * (3 * C_) + h * D_;
    if (tid < 64) sq[tid] = qp[tid];
    __syncthreads();

    for (int j = tid; j < cnt; j += 128) {
        const float* kp = g_qkv + ((size_t)b * M_ + start + j) * (3 * C_) + C_ + h * D_;
        float acc = 0.f;
#pragma unroll
        for (int d0 = 0; d0 < D_; d0 += 4) {
            float4 kv = *(const float4*)(kp + d0);
            acc += sq[d0] * kv.x + sq[d0 + 1] * kv.y + sq[d0 + 2] * kv.z + sq[d0 + 3] * kv.w;
        }
        sc[j] = acc * SCALE_;
    }
    __syncthreads();

    float m = -INFINITY;
    for (int j = tid; j < cnt; j += 128) m = fmaxf(m, sc[j]);
    m = warpMax(m);
    if ((tid & 31) == 0) sred[tid >> 5] = m;
    __syncthreads();
    m = fmaxf(fmaxf(sred[0], sred[1]), fmaxf(sred[2], sred[3]));
    __syncthreads();

    float ls = 0.f;
    for (int j = tid; j < cnt; j += 128) {
        float pv = expf(sc[j] - m);
        sc[j] = pv;
        ls += pv;
    }
    ls = warpSum(ls);
    if ((tid & 31) == 0) sred[tid >> 5] = ls;
    __syncthreads();
    float ssum = sred[0] + sred[1] + sred[2] + sred[3];

    int d = tid & 63, grp = tid >> 6;
    float acc = 0.f;
    for (int j = grp; j < cnt; j += 2)
        acc += sc[j] * g_qkv[((size_t)b * M_ + start + j) * (3 * C_) + 2 * C_ + h * D_ + d];
    oacc[tid] = acc;
    __syncthreads();

    float* dst = g_clsp + ((size_t)bh * 8 + chunk) * 66;
    if (tid < 64) dst[2 + tid] = oacc[tid] + oacc[tid + 64];
    if (tid == 0) { dst[0] = m; dst[1] = ssum; }
}

__global__ void attn_cls_comb_kernel() {
    int bh = blockIdx.x;
    int b = bh / H_, h = bh % H_;
    int d = threadIdx.x;
    const float* src = g_clsp + (size_t)bh * 8 * 66;
    float M = 0.f;
#pragma unroll
    for (int c = 0; c < 8; ++c) M = fmaxf(M, src[c * 66]);
    float denom = expf(-M);
    float o = 0.f;
#pragma unroll
    for (int c = 0; c < 8; ++c) {
        float w = expf(src[c * 66] - M);
        denom += src[c * 66 + 1] * w;
        o += src[c * 66 + 2 + d] * w;
    }
    g_att[(size_t)(b * M_) * C_ + h * D_ + d] = rtf(o / denom);
}

// Pad query.
__global__ void attn_pad_kernel() {
    int b = blockIdx.y;
    int cg = blockIdx.x;
    int tid = threadIdx.x;
    int cl = tid & 31;
    int rg = tid >> 5;
    int ch = cg * 32 + cl;
    const float* base = g_qkv + (size_t)b * M_ * (3 * C_) + 2 * C_ + ch;
    float acc = 0.f;
    for (int mrow = rg; mrow < 1025; mrow += 8)
        acc += base[(size_t)mrow * (3 * C_)];
    __shared__ float sm2[8][32];
    sm2[rg][cl] = acc;
    __syncthreads();
    if (tid < 32) {
        float a = 0.f;
#pragma unroll
        for (int rr = 0; rr < 8; ++rr) a += sm2[rr][tid];
        g_att[((size_t)b * M_ + 1025) * C_ + cg * 32 + tid] = rtf(a * (1.0f / 1026.0f));
    }
}

// Copy LN2 row 0 (CLS) into g_cat row 0 of each batch.
__global__ void cls_copy_kernel() {
    int b = blockIdx.x;
    int t = threadIdx.x;
    ((float4*)(g_cat + (size_t)b * CAT_ * C_))[t] =
        ((const float4*)(g_h2 + (size_t)b * 1025 * C_))[t];
}

// ---------------------------------------------------------------------------
// Launch
// ---------------------------------------------------------------------------
extern "C" void kernel_launch(void* const* d_in, const int* in_sizes, int n_in,
                              void* d_out, int out_size) {
    const float* x      = (const float*)d_in[0];
    const float* n1w    = (const float*)d_in[1];
    const float* n1b    = (const float*)d_in[2];
    const float* qkv_w  = (const float*)d_in[3];
    const float* proj_w = (const float*)d_in[4];
    const float* proj_b = (const float*)d_in[5];
    const float* n2w    = (const float*)d_in[6];
    const float* n2b    = (const float*)d_in[7];
    const float* pool_w = (const float*)d_in[8];
    const float* pool_b = (const float*)d_in[9];
    const float* n3w    = (const float*)d_in[10];
    const float* n3b    = (const float*)d_in[11];
    const float* fc1_w  = (const float*)d_in[12];
    const float* fc1_b  = (const float*)d_in[13];
    const float* fc2_w  = (const float*)d_in[14];
    const float* fc2_b  = (const float*)d_in[15];
    float* out = (float*)d_out;

    float *h1, *h1r, *qkvp, *att, *res, *h2, *cat, *h3, *fc1o;
    float *wqkv, *wproj, *wpool, *wfc1, *wfc2;
    cudaGetSymbolAddress((void**)&h1,    g_h1);
    cudaGetSymbolAddress((void**)&h1r,   g_h1r);
    cudaGetSymbolAddress((void**)&qkvp,  g_qkv);
    cudaGetSymbolAddress((void**)&att,   g_att);
    cudaGetSymbolAddress((void**)&res,   g_res);
    cudaGetSymbolAddress((void**)&h2,    g_h2);
    cudaGetSymbolAddress((void**)&cat,   g_cat);
    cudaGetSymbolAddress((void**)&h3,    g_h3);
    cudaGetSymbolAddress((void**)&fc1o,  g_fc1);
    cudaGetSymbolAddress((void**)&wqkv,  g_wqkv);
    cudaGetSymbolAddress((void**)&wproj, g_wproj);
    cudaGetSymbolAddress((void**)&wpool, g_wpool);
    cudaGetSymbolAddress((void**)&wfc1,  g_wfc1);
    cudaGetSymbolAddress((void**)&wfc2,  g_wfc2);

    static int smemSet = 0;
    if (!smemSet) {
        cudaFuncSetAttribute((const void*)&tgemm_kernel<0,0>,
                             cudaFuncAttributeMaxDynamicSharedMemorySize, TG_SMEM);
        cudaFuncSetAttribute((const void*)&tgemm_kernel<1,1>,
                             cudaFuncAttributeMaxDynamicSharedMemorySize, TG_SMEM);
        smemSet = 1;
    }

    const int MROWS = B_ * M_;        // 8208
    const int PROWS = B_ * W_;        // 2048
    const int CROWS = B_ * CAT_;      // 2056

    // prep: weights rounding + key table, one launch
    prep_kernel<<<WB_ + 4, 256>>>(
        (const float4*)qkv_w, (const float4*)proj_w, (const float4*)pool_w,
        (const float4*)fc1_w, (const float4*)fc2_w);

    // LN1: exact -> h1, rounded -> h1r; row 1025 zeroed in both
    ln_kernel<<<dim3(1026, B_), 128>>>(x, h1, n1w, n1b, 1025, M_, 1025, 0, h1r);

    tgemm_kernel<0,0><<<dim3(1152 / 64, (MROWS + 127) / 128), 256, TG_SMEM>>>(
        MROWS, 3 * C_, C_, h1r, wqkv, nullptr, nullptr, qkvp, 0, 0);

    // 2 heads per warp: B * 3 * 1024 warps / 8 per block = 3072 blocks
    attn_token_kernel<<<(B_ * 3 * NT_) / 8, 256>>>();
    attn_cls_part_kernel<<<dim3(8, B_ * H_), 128>>>();
    attn_cls_comb_kernel<<<B_ * H_, 64>>>();
    attn_pad_kernel<<<dim3(12, B_), 256>>>();

    tgemm_kernel<0,0><<<dim3(C_ / 64, (MROWS + 127) / 128), 256, TG_SMEM>>>(
        MROWS, C_, C_, att, wproj, proj_b, h1, res, 0, 0);

    // LN2 output rounded (pool GEMM A)
    ln_kernel<<<dim3(1025, B_), 128>>>(res, h2, n2w, n2b, M_, 1025, 1025, 1, nullptr);

    // pool GEMM with fused gather, writes directly into g_cat rows 1..256
    tgemm_kernel<1,1><<<dim3(C_ / 64, PROWS / 128), 256, TG_SMEM>>>(
        PROWS, C_, 9 * C_, h2, wpool, pool_b, nullptr, cat, 0, 0);
    cls_copy_kernel<<<B_, 96>>>();

    // LN3 output rounded (fc1 GEMM A)
    ln_kernel<<<dim3(CAT_, B_), 128>>>(cat, h3, n3w, n3b, CAT_, CAT_, CAT_, 1, nullptr);

    tgemm_kernel<0,0><<<dim3(HID_ / 64, (CROWS + 127) / 128), 256, TG_SMEM>>>(
        CROWS, HID_, C_, h3, wfc1, fc1_b, nullptr, fc1o, 1, 1);
    tgemm_kernel<0,0><<<dim3(C_ / 64, (CROWS + 127) / 128), 256, TG_SMEM>>>(
        CROWS, C_, HID_, fc1o, wfc2, fc2_b, nullptr, out, 0, 0);
}

// round 17
// speedup vs baseline: 1.3152x; 1.0330x over previous
#include <cuda_runtime.h>
#include <math.h>

#define B_    8
#define M_    1026
#define NT_   1024
#define C_    384
#define H_    6
#define D_    64
#define HID_  1536
#define W_    256
#define CAT_  257
#define SCALE_ 0.4082482904638631f

// ---------------------------------------------------------------------------
// Scratch
// ---------------------------------------------------------------------------
__device__ float g_h1  [B_*M_*C_];        // LN1 exact (proj residual)
__device__ float g_h1r [B_*M_*C_];        // LN1 tf32-rounded (QKV GEMM A)
__device__ float g_qkv [B_*M_*3*C_];
__device__ float g_att [B_*M_*C_];        // tf32-rounded at write
__device__ float g_res [B_*M_*C_];
__device__ float g_h2  [B_*(NT_+1)*C_];   // tf32-rounded (pool GEMM A)
__device__ float g_cat [B_*CAT_*C_];
__device__ float g_h3  [B_*CAT_*C_];      // tf32-rounded (fc1 GEMM A)
__device__ float g_fc1 [B_*CAT_*HID_];    // tf32-rounded (fc2 GEMM A)
__device__ float g_clsp[48*8*66];
// pre-rounded weights
__device__ float g_wqkv [3*C_*C_];
__device__ float g_wproj[C_*C_];
__device__ float g_wpool[C_*9*C_];
__device__ float g_wfc1 [HID_*C_];
__device__ float g_wfc2 [C_*HID_];
// precomputed sparse-attention key table
__device__ int   g_keys[NT_*32];
__device__ int   g_kcnt[NT_];

// ---------------------------------------------------------------------------
// Helpers
// ---------------------------------------------------------------------------
__device__ __forceinline__ float warpSum(float v) {
#pragma unroll
    for (int o = 16; o > 0; o >>= 1) v += __shfl_xor_sync(0xffffffffu, v, o);
    return v;
}
__device__ __forceinline__ float warpMax(float v) {
#pragma unroll
    for (int o = 16; o > 0; o >>= 1) v = fmaxf(v, __shfl_xor_sync(0xffffffffu, v, o));
    return v;
}
__device__ __forceinline__ unsigned f2tf(float f) {
    unsigned u;
    asm("cvt.rna.tf32.f32 %0, %1;" : "=r"(u) : "f"(f));
    return u;
}
__device__ __forceinline__ float rtf(float f) { return __uint_as_float(f2tf(f)); }
__device__ __forceinline__ void cpasync16(void* smem_dst, const void* gsrc, bool pred) {
    unsigned saddr = (unsigned)__cvta_generic_to_shared(smem_dst);
    int sz = pred ? 16 : 0;
    asm volatile("cp.async.ca.shared.global [%0], [%1], 16, %2;\n"
                 :: "r"(saddr), "l"(gsrc), "r"(sz));
}
__device__ __forceinline__ void ldsm4(unsigned& r0, unsigned& r1, unsigned& r2, unsigned& r3,
                                      unsigned addr) {
    asm volatile("ldmatrix.sync.aligned.m8n8.x4.shared.b16 {%0,%1,%2,%3}, [%4];\n"
                 : "=r"(r0), "=r"(r1), "=r"(r2), "=r"(r3) : "r"(addr));
}

// ---------------------------------------------------------------------------
// Merged prep: weight rounding (blocks 0..WB-1) + key table (last 4 blocks).
// ---------------------------------------------------------------------------
#define WQ4 110592
#define WP4 36864
#define WO4 331776
#define W14 147456
#define W24 147456
#define WT4 (WQ4+WP4+WO4+W14+W24)   // 774144
#define WB_ ((WT4 + 255) / 256)     // 3024

__global__ void prep_kernel(const float4* __restrict__ qkv,
                            const float4* __restrict__ proj,
                            const float4* __restrict__ pool,
                            const float4* __restrict__ f1,
                            const float4* __restrict__ f2) {
    int blk = blockIdx.x;
    int tid = threadIdx.x;
    if (blk < WB_) {
        int i = blk * 256 + tid;
        if (i >= WT4) return;
        const float4* src;
        float4* dst;
        int o = i;
        if (o < WQ4)               { src = qkv  + o; dst = (float4*)g_wqkv  + o; }
        else if ((o -= WQ4) < WP4) { src = proj + o; dst = (float4*)g_wproj + o; }
        else if ((o -= WP4) < WO4) { src = pool + o; dst = (float4*)g_wpool + o; }
        else if ((o -= WO4) < W14) { src = f1   + o; dst = (float4*)g_wfc1  + o; }
        else { o -= W14;             src = f2   + o; dst = (float4*)g_wfc2  + o; }
        float4 v = *src;
        *dst = make_float4(rtf(v.x), rtf(v.y), rtf(v.z), rtf(v.w));
        return;
    }
    // key-table blocks: t in [0, 1024)
    int t = (blk - WB_) * 256 + tid;
    int r = t >> 5, c = t & 31;
    int rl[5], cl[5];
    int nr = 0, nc = 0;
#pragma unroll
    for (int dr = -2; dr <= 2; ++dr) {
        int rp = r + dr;
        if (rp < 0 || rp > 31) continue;
        int lo = (r > rp ? r : rp) - 1; if (lo < 0) lo = 0;
        int hi = (r < rp ? r : rp) + 1; if (hi > 30) hi = 30;
        int fe = lo + (lo & 1);
        if (fe <= hi) rl[nr++] = rp;
    }
#pragma unroll
    for (int dc = -2; dc <= 2; ++dc) {
        int cp = c + dc;
        if (cp < 0 || cp > 31) continue;
        int lo = (c > cp ? c : cp) - 1; if (lo < 0) lo = 0;
        int hi = (c < cp ? c : cp) + 1; if (hi > 30) hi = 30;
        int fe = lo + (lo & 1);
        if (fe <= hi) cl[nc++] = cp;
    }
    int cnt = 1 + nr * nc;
    g_kcnt[t] = cnt;
    for (int j = 0; j < 32; ++j) {
        int key = 0;
        if (j >= 1 && j < cnt) {
            int i = j - 1;
            key = rl[i / nc] * 32 + cl[i % nc] + 1;
        }
        g_keys[t * 32 + j] = key * (3 * C_);
    }
}

// ---------------------------------------------------------------------------
// LayerNorm; rows >= inRows emit zeros; roundMain rounds; outR = rounded copy;
// clsDst: duplicate row 0 into clsDst + b*CAT_*C_ (LN2 -> g_cat fusion).
// ---------------------------------------------------------------------------
__global__ void ln_kernel(const float* __restrict__ in, float* __restrict__ out,
                          const float* __restrict__ gw, const float* __restrict__ gb,
                          int inStride, int outStride, int inRows, int roundMain,
                          float* __restrict__ outR, float* __restrict__ clsDst) {
    int i = blockIdx.x, b = blockIdx.y;
    int tid = threadIdx.x;
    float* yr = out + ((size_t)b * outStride + i) * C_;
    if (i >= inRows) {
        yr[tid] = 0.f; yr[tid + 128] = 0.f; yr[tid + 256] = 0.f;
        if (outR) {
            float* zr = outR + ((size_t)b * outStride + i) * C_;
            zr[tid] = 0.f; zr[tid + 128] = 0.f; zr[tid + 256] = 0.f;
        }
        return;
    }
    const float* xr = in + ((size_t)b * inStride + i) * C_;
    float v0 = xr[tid], v1 = xr[tid + 128], v2 = xr[tid + 256];
    __shared__ float sm[4];
    float s = warpSum(v0 + v1 + v2);
    if ((tid & 31) == 0) sm[tid >> 5] = s;
    __syncthreads();
    float mu = (sm[0] + sm[1] + sm[2] + sm[3]) * (1.f / 384.f);
    float d0 = v0 - mu, d1 = v1 - mu, d2 = v2 - mu;
    __syncthreads();
    float q = warpSum(d0 * d0 + d1 * d1 + d2 * d2);
    if ((tid & 31) == 0) sm[tid >> 5] = q;
    __syncthreads();
    float var = (sm[0] + sm[1] + sm[2] + sm[3]) * (1.f / 384.f);
    float rs = rsqrtf(var + 1e-5f);
    float r0 = d0 * rs * gw[tid]       + gb[tid];
    float r1 = d1 * rs * gw[tid + 128] + gb[tid + 128];
    float r2 = d2 * rs * gw[tid + 256] + gb[tid + 256];
    if (roundMain) { r0 = rtf(r0); r1 = rtf(r1); r2 = rtf(r2); }
    yr[tid]       = r0;
    yr[tid + 128] = r1;
    yr[tid + 256] = r2;
    if (outR) {
        float* zr = outR + ((size_t)b * outStride + i) * C_;
        zr[tid]       = rtf(r0);
        zr[tid + 128] = rtf(r1);
        zr[tid + 256] = rtf(r2);
    }
    if (clsDst && i == 0) {
        float* cr = clsDst + (size_t)b * CAT_ * C_;
        cr[tid]       = r0;
        cr[tid + 128] = r1;
        cr[tid + 256] = r2;
    }
}

// ---------------------------------------------------------------------------
// TF32 tensor-core GEMM: 128x64x32, 256 threads, 2-stage cp.async,
// ldmatrix.x4, cvt-free mainloop. GATHER = pool A gather.
// CATMODE = output row remap row+row/256+1. roundOut rounds stores.
// ---------------------------------------------------------------------------
#define KP_ 36
#define TG_SMEM ((2*128*KP_ + 2*64*KP_) * 4)   // 55296 bytes
#define SA_STAGE_BYTES (128*KP_*4)
#define SB_STAGE_BYTES (64*KP_*4)
#define SB_BASE_BYTES  (2*128*KP_*4)

template<int GATHER, int CATMODE>
__global__ void __launch_bounds__(256)
tgemm_kernel(int M, int N, int K,
             const float* __restrict__ A, const float* __restrict__ Wt,
             const float* __restrict__ bias, const float* __restrict__ resid,
             float* __restrict__ Cc, int doGelu, int roundOut) {
    extern __shared__ float dyn[];
    float (*sA)[128][KP_] = (float(*)[128][KP_])dyn;
    float (*sB)[64][KP_]  = (float(*)[64][KP_])(dyn + 2 * 128 * KP_);

    int tid  = threadIdx.x;
    int lane = tid & 31;
    int wid  = tid >> 5;
    int wm   = wid & 3;
    int wn   = wid >> 2;
    int lr   = lane >> 2;
    int lc   = lane & 3;

    int bm = blockIdx.y * 128;
    int bn = blockIdx.x * 64;

    int ldRow = tid >> 3;
    int ldC4  = tid & 7;

    unsigned smemU = (unsigned)__cvta_generic_to_shared(dyn);
    int lm = lane >> 3;
    int lrr = lane & 7;
    unsigned aAddr[2];
#pragma unroll
    for (int mt = 0; mt < 2; ++mt)
        aAddr[mt] = smemU +
            ((unsigned)((wm * 32 + mt * 16 + (lm & 1) * 8 + lrr) * KP_ + (lm >> 1) * 4)) * 4u;
    unsigned bAddr = smemU + SB_BASE_BYTES +
        ((unsigned)((wn * 32 + lm * 8 + lrr) * KP_)) * 4u;

    float acc[2][4][4];
#pragma unroll
    for (int mt = 0; mt < 2; ++mt)
#pragma unroll
        for (int nt = 0; nt < 4; ++nt)
#pragma unroll
            for (int e = 0; e < 4; ++e) acc[mt][nt][e] = 0.f;

    int nIter = K >> 5;

    auto loadTile = [&](int it, int s) {
        int k0 = it << 5;
        if (!GATHER) {
#pragma unroll
            for (int i = 0; i < 4; ++i) {
                int r = ldRow + i * 32;
                int gr = bm + r;
                bool p = gr < M;
                const float* src = A + (size_t)(p ? gr : 0) * K + k0 + ldC4 * 4;
                cpasync16(&sA[s][r][ldC4 * 4], src, p);
            }
        } else {
            int kk = k0 / 384;
            int c0 = k0 - kk * 384;
#pragma unroll
            for (int i = 0; i < 4; ++i) {
                int r = ldRow + i * 32;
                int gr = bm + r;
                int b = gr >> 8, w = gr & 255;
                int wi = w >> 4, wj = w & 15;
                int rr = 2 * wi + kk / 3 - 1;
                int cc = 2 * wj + kk % 3 - 1;
                int hrow = (rr < 0 || cc < 0) ? 1024 : rr * 32 + cc + 1;
                const float* src = A + ((size_t)b * 1025 + hrow) * 384 + c0 + ldC4 * 4;
                cpasync16(&sA[s][r][ldC4 * 4], src, true);
            }
        }
#pragma unroll
        for (int i = 0; i < 2; ++i) {
            int n = ldRow + i * 32;
            int gn = bn + n;
            bool p = gn < N;
            const float* src = Wt + (size_t)(p ? gn : 0) * K + k0 + ldC4 * 4;
            cpasync16(&sB[s][n][ldC4 * 4], src, p);
        }
    };

    loadTile(0, 0);
    asm volatile("cp.async.commit_group;\n");

    for (int it = 0; it < nIter; ++it) {
        int s = it & 1;
        if (it + 1 < nIter) {
            loadTile(it + 1, s ^ 1);
            asm volatile("cp.async.commit_group;\n");
            asm volatile("cp.async.wait_group 1;\n");
        } else {
            asm volatile("cp.async.wait_group 0;\n");
        }
        __syncthreads();

        unsigned sAoff = (unsigned)(s * SA_STAGE_BYTES);
        unsigned sBoff = (unsigned)(s * SB_STAGE_BYTES);

#pragma unroll
        for (int ks = 0; ks < 4; ++ks) {
            unsigned kOff = (unsigned)(ks * 8 * 4);
            unsigned a[2][4], bf[4][2];
#pragma unroll
            for (int mt = 0; mt < 2; ++mt)
                ldsm4(a[mt][0], a[mt][1], a[mt][2], a[mt][3],
                      aAddr[mt] + sAoff + kOff);
            {
                unsigned b0, b1, b2, b3;
                ldsm4(b0, b1, b2, b3, bAddr + sBoff + kOff);
                bf[0][0] = b0; bf[1][0] = b1; bf[2][0] = b2; bf[3][0] = b3;
                ldsm4(b0, b1, b2, b3, bAddr + sBoff + kOff + 16);
                bf[0][1] = b0; bf[1][1] = b1; bf[2][1] = b2; bf[3][1] = b3;
            }
#pragma unroll
            for (int mt = 0; mt < 2; ++mt)
#pragma unroll
                for (int nt = 0; nt < 4; ++nt) {
                    asm volatile(
                        "mma.sync.aligned.m16n8k8.row.col.f32.tf32.tf32.f32 "
                        "{%0,%1,%2,%3}, {%4,%5,%6,%7}, {%8,%9}, {%0,%1,%2,%3};\n"
                        : "+f"(acc[mt][nt][0]), "+f"(acc[mt][nt][1]),
                          "+f"(acc[mt][nt][2]), "+f"(acc[mt][nt][3])
                        : "r"(a[mt][0]), "r"(a[mt][1]), "r"(a[mt][2]), "r"(a[mt][3]),
                          "r"(bf[nt][0]), "r"(bf[nt][1]));
                }
        }
        __syncthreads();
    }

#pragma unroll
    for (int mt = 0; mt < 2; ++mt) {
#pragma unroll
        for (int nt = 0; nt < 4; ++nt) {
            int col = bn + wn * 32 + nt * 8 + 2 * lc;
            float bx = 0.f, by = 0.f;
            if (bias) { bx = bias[col]; by = bias[col + 1]; }
#pragma unroll
            for (int half = 0; half < 2; ++half) {
                int row = bm + wm * 32 + mt * 16 + lr + half * 8;
                if (row >= M) continue;
                float vx = acc[mt][nt][2 * half + 0] + bx;
                float vy = acc[mt][nt][2 * half + 1] + by;
                if (resid) {
                    const float2 rv = *(const float2*)(resid + (size_t)row * N + col);
                    vx += rv.x; vy += rv.y;
                }
                if (doGelu) {
                    vx = 0.5f * vx * (1.f + erff(vx * 0.70710678118654752f));
                    vy = 0.5f * vy * (1.f + erff(vy * 0.70710678118654752f));
                }
                if (roundOut) { vx = rtf(vx); vy = rtf(vy); }
                int orow = CATMODE ? (row + (row >> 8) + 1) : row;
                *(float2*)(Cc + (size_t)orow * N + col) = make_float2(vx, vy);
            }
        }
    }
}

// ---------------------------------------------------------------------------
// Fused attention super-kernel (one launch, 3552 blocks x 256 threads):
//   blocks [0, 3072):      token path, 2 heads per warp
//   blocks [3072, 3456):   CLS split-K partials (256-thread variant)
//   blocks [3456, 3552):   pad-row path
// All depend only on g_qkv; outputs disjoint.
// ---------------------------------------------------------------------------
#define ATK_BLKS (B_ * 3 * NT_ / 8)    // 3072
#define CLS_BLKS (8 * B_ * H_)         // 384
#define PAD_BLKS (12 * B_)             // 96

__global__ void attn_fused_kernel() {
    int blk = blockIdx.x;
    int tid = threadIdx.x;
    int lane = tid & 31;

    if (blk < ATK_BLKS) {
        // ------------------ token path ------------------
        int gw = blk * 8 + (tid >> 5);
        int t  = gw & 1023;
        int bh = gw >> 10;          // 0..23
        int hp = bh % 3;            // heads hp and hp+3
        int b  = bh / 3;

        int key_off = g_keys[t * 32 + lane];
        int cnt     = g_kcnt[t];

        const float* base = g_qkv + (size_t)b * M_ * (3 * C_);
        const float* qp = base + (size_t)(t + 1) * (3 * C_) + hp * D_;
        int hl = lane & 15;
        float4 qv0 = *(const float4*)(qp + hl * 4);
        float4 qv1 = *(const float4*)(qp + 3 * D_ + hl * 4);
        const float* kbase = base + C_ + hp * D_;

        float s0 = -INFINITY, s1 = -INFINITY;
        for (int j0 = 0; j0 < 26; j0 += 2) {
            if (j0 >= cnt) break;
            int ka = __shfl_sync(0xffffffffu, key_off, j0);
            int kb = __shfl_sync(0xffffffffu, key_off, j0 + 1);
            int kidx = (lane < 16) ? ka : kb;
            const float* kp = kbase + kidx + hl * 4;
            float4 kv0 = *(const float4*)(kp);
            float4 kv1 = *(const float4*)(kp + 3 * D_);
            float d0 = qv0.x * kv0.x + qv0.y * kv0.y + qv0.z * kv0.z + qv0.w * kv0.w;
            float d1 = qv1.x * kv1.x + qv1.y * kv1.y + qv1.z * kv1.z + qv1.w * kv1.w;
#pragma unroll
            for (int o = 8; o > 0; o >>= 1) {
                d0 += __shfl_xor_sync(0xffffffffu, d0, o);
                d1 += __shfl_xor_sync(0xffffffffu, d1, o);
            }
            float dx0 = __shfl_xor_sync(0xffffffffu, d0, 16);
            float dx1 = __shfl_xor_sync(0xffffffffu, d1, 16);
            float da0 = (lane < 16) ? d0 : dx0;
            float db0 = (lane < 16) ? dx0 : d0;
            float da1 = (lane < 16) ? d1 : dx1;
            float db1 = (lane < 16) ? dx1 : d1;
            if (lane == j0)     { s0 = da0 * SCALE_; s1 = da1 * SCALE_; }
            if (lane == j0 + 1) { s0 = db0 * SCALE_; s1 = db1 * SCALE_; }
        }
        if (lane >= cnt) { s0 = -INFINITY; s1 = -INFINITY; }

        float m0 = fmaxf(warpMax(s0), 0.f);
        float m1 = fmaxf(warpMax(s1), 0.f);
        float p0 = (lane < cnt) ? expf(s0 - m0) : 0.f;
        float p1 = (lane < cnt) ? expf(s1 - m1) : 0.f;
        float inv0 = 1.f / (warpSum(p0) + expf(-m0));
        float inv1 = 1.f / (warpSum(p1) + expf(-m1));

        const float* vbase = base + 2 * C_ + hp * D_;
        float o00 = 0.f, o01 = 0.f, o10 = 0.f, o11 = 0.f;
        for (int j = 0; j < cnt; ++j) {
            float pj0 = __shfl_sync(0xffffffffu, p0, j);
            float pj1 = __shfl_sync(0xffffffffu, p1, j);
            int   kj  = __shfl_sync(0xffffffffu, key_off, j);
            const float* vp = vbase + kj + 2 * lane;
            float2 v0 = *(const float2*)(vp);
            float2 v1 = *(const float2*)(vp + 3 * D_);
            o00 += pj0 * v0.x; o01 += pj0 * v0.y;
            o10 += pj1 * v1.x; o11 += pj1 * v1.y;
        }
        float* op = g_att + ((size_t)b * M_ + (t + 1)) * C_ + hp * D_;
        *(float2*)(op + 2 * lane)          = make_float2(rtf(o00 * inv0), rtf(o01 * inv0));
        *(float2*)(op + 3 * D_ + 2 * lane) = make_float2(rtf(o10 * inv1), rtf(o11 * inv1));
        return;
    }

    if (blk < ATK_BLKS + CLS_BLKS) {
        // ------------------ CLS split-K partials (256 threads) ------------------
        int q = blk - ATK_BLKS;
        int chunk = q & 7;
        int bh    = q >> 3;          // 0..47
        int b = bh / H_, h = bh % H_;
        int start = chunk * 129;
        int end   = start + 129; if (end > 1025) end = 1025;
        int cnt   = end - start;

        __shared__ float sq[64];
        __shared__ float sc[132];
        __shared__ float sred[8];
        __shared__ float oacc[256];

        const float* qp = g_qkv + (size_t)(b * M_) * (3 * C_) + h * D_;
        if (tid < 64) sq[tid] = qp[tid];
        __syncthreads();

        for (int j = tid; j < cnt; j += 256) {
            const float* kp = g_qkv + ((size_t)b * M_ + start + j) * (3 * C_) + C_ + h * D_;
            float acc = 0.f;
#pragma unroll
            for (int d0 = 0; d0 < D_; d0 += 4) {
                float4 kv = *(const float4*)(kp + d0);
                acc += sq[d0] * kv.x + sq[d0 + 1] * kv.y + sq[d0 + 2] * kv.z + sq[d0 + 3] * kv.w;
            }
            sc[j] = acc * SCALE_;
        }
        __syncthreads();

        float m = -INFINITY;
        for (int j = tid; j < cnt; j += 256) m = fmaxf(m, sc[j]);
        m = warpMax(m);
        if ((tid & 31) == 0) sred[tid >> 5] = m;
        __syncthreads();
        m = sred[0];
#pragma unroll
        for (int wr = 1; wr < 8; ++wr) m = fmaxf(m, sred[wr]);
        __syncthreads();

        float ls = 0.f;
        for (int j = tid; j < cnt; j += 256) {
            float pv = expf(sc[j] - m);
            sc[j] = pv;
            ls += pv;
        }
        ls = warpSum(ls);
        if ((tid & 31) == 0) sred[tid >> 5] = ls;
        __syncthreads();
        float ssum = 0.f;
#pragma unroll
        for (int wr = 0; wr < 8; ++wr) ssum += sred[wr];

        int d = tid & 63, grp = tid >> 6;   // 4 row groups
        float acc = 0.f;
        for (int j = grp; j < cnt; j += 4)
            acc += sc[j] * g_qkv[((size_t)b * M_ + start + j) * (3 * C_) + 2 * C_ + h * D_ + d];
        oacc[tid] = acc;
        __syncthreads();

        float* dst = g_clsp + ((size_t)bh * 8 + chunk) * 66;
        if (tid < 64)
            dst[2 + tid] = oacc[tid] + oacc[tid + 64] + oacc[tid + 128] + oacc[tid + 192];
        if (tid == 0) { dst[0] = m; dst[1] = ssum; }
        return;
    }

    {
        // ------------------ pad-row path ------------------
        int q = blk - (ATK_BLKS + CLS_BLKS);
        int cg = q % 12;
        int b  = q / 12;
        int cl = tid & 31;
        int rg = tid >> 5;
        int ch = cg * 32 + cl;
        const float* base = g_qkv + (size_t)b * M_ * (3 * C_) + 2 * C_ + ch;
        float acc = 0.f;
        for (int mrow = rg; mrow < 1025; mrow += 8)
            acc += base[(size_t)mrow * (3 * C_)];
        __shared__ float sm2[8][32];
        sm2[rg][cl] = acc;
        __syncthreads();
        if (tid < 32) {
            float a = 0.f;
#pragma unroll
            for (int rr = 0; rr < 8; ++rr) a += sm2[rr][tid];
            g_att[((size_t)b * M_ + 1025) * C_ + cg * 32 + tid] = rtf(a * (1.0f / 1026.0f));
        }
    }
}

// ---------------------------------------------------------------------------
// CLS combine (needs all cls partials -> separate launch).
// ---------------------------------------------------------------------------
__global__ void attn_cls_comb_kernel() {
    int bh = blockIdx.x;
    int b = bh / H_, h = bh % H_;
    int d = threadIdx.x;
    const float* src = g_clsp + (size_t)bh * 8 * 66;
    float M = 0.f;
#pragma unroll
    for (int c = 0; c < 8; ++c) M = fmaxf(M, src[c * 66]);
    float denom = expf(-M);
    float o = 0.f;
#pragma unroll
    for (int c = 0; c < 8; ++c) {
        float w = expf(src[c * 66] - M);
        denom += src[c * 66 + 1] * w;
        o += src[c * 66 + 2 + d] * w;
    }
    g_att[(size_t)(b * M_) * C_ + h * D_ + d] = rtf(o / denom);
}

// ---------------------------------------------------------------------------
// Launch
// ---------------------------------------------------------------------------
extern "C" void kernel_launch(void* const* d_in, const int* in_sizes, int n_in,
                              void* d_out, int out_size) {
    const float* x      = (const float*)d_in[0];
    const float* n1w    = (const float*)d_in[1];
    const float* n1b    = (const float*)d_in[2];
    const float* qkv_w  = (const float*)d_in[3];
    const float* proj_w = (const float*)d_in[4];
    const float* proj_b = (const float*)d_in[5];
    const float* n2w    = (const float*)d_in[6];
    const float* n2b    = (const float*)d_in[7];
    const float* pool_w = (const float*)d_in[8];
    const float* pool_b = (const float*)d_in[9];
    const float* n3w    = (const float*)d_in[10];
    const float* n3b    = (const float*)d_in[11];
    const float* fc1_w  = (const float*)d_in[12];
    const float* fc1_b  = (const float*)d_in[13];
    const float* fc2_w  = (const float*)d_in[14];
    const float* fc2_b  = (const float*)d_in[15];
    float* out = (float*)d_out;

    float *h1, *h1r, *qkvp, *att, *res, *h2, *cat, *h3, *fc1o;
    float *wqkv, *wproj, *wpool, *wfc1, *wfc2;
    cudaGetSymbolAddress((void**)&h1,    g_h1);
    cudaGetSymbolAddress((void**)&h1r,   g_h1r);
    cudaGetSymbolAddress((void**)&qkvp,  g_qkv);
    cudaGetSymbolAddress((void**)&att,   g_att);
    cudaGetSymbolAddress((void**)&res,   g_res);
    cudaGetSymbolAddress((void**)&h2,    g_h2);
    cudaGetSymbolAddress((void**)&cat,   g_cat);
    cudaGetSymbolAddress((void**)&h3,    g_h3);
    cudaGetSymbolAddress((void**)&fc1o,  g_fc1);
    cudaGetSymbolAddress((void**)&wqkv,  g_wqkv);
    cudaGetSymbolAddress((void**)&wproj, g_wproj);
    cudaGetSymbolAddress((void**)&wpool, g_wpool);
    cudaGetSymbolAddress((void**)&wfc1,  g_wfc1);
    cudaGetSymbolAddress((void**)&wfc2,  g_wfc2);

    static int smemSet = 0;
    if (!smemSet) {
        cudaFuncSetAttribute((const void*)&tgemm_kernel<0,0>,
                             cudaFuncAttributeMaxDynamicSharedMemorySize, TG_SMEM);
        cudaFuncSetAttribute((const void*)&tgemm_kernel<1,1>,
                             cudaFuncAttributeMaxDynamicSharedMemorySize, TG_SMEM);
        smemSet = 1;
    }

    const int MROWS = B_ * M_;        // 8208
    const int PROWS = B_ * W_;        // 2048
    const int CROWS = B_ * CAT_;      // 2056

    // prep: weights rounding + key table, one launch
    prep_kernel<<<WB_ + 4, 256>>>(
        (const float4*)qkv_w, (const float4*)proj_w, (const float4*)pool_w,
        (const float4*)fc1_w, (const float4*)fc2_w);

    // LN1: exact -> h1, rounded -> h1r; row 1025 zeroed in both
    ln_kernel<<<dim3(1026, B_), 128>>>(x, h1, n1w, n1b, 1025, M_, 1025, 0, h1r, nullptr);

    tgemm_kernel<0,0><<<dim3(1152 / 64, (MROWS + 127) / 128), 256, TG_SMEM>>>(
        MROWS, 3 * C_, C_, h1r, wqkv, nullptr, nullptr, qkvp, 0, 0);

    // fused attention: token + CLS partials + pad, one launch
    attn_fused_kernel<<<ATK_BLKS + CLS_BLKS + PAD_BLKS, 256>>>();
    attn_cls_comb_kernel<<<B_ * H_, 64>>>();

    tgemm_kernel<0,0><<<dim3(C_ / 64, (MROWS + 127) / 128), 256, TG_SMEM>>>(
        MROWS, C_, C_, att, wproj, proj_b, h1, res, 0, 0);

    // LN2: rounded output -> h2; row 0 duplicated into g_cat row 0
    ln_kernel<<<dim3(1025, B_), 128>>>(res, h2, n2w, n2b, M_, 1025, 1025, 1, nullptr, cat);

    // pool GEMM with fused gather, writes directly into g_cat rows 1..256
    tgemm_kernel<1,1><<<dim3(C_ / 64, PROWS / 128), 256, TG_SMEM>>>(
        PROWS, C_, 9 * C_, h2, wpool, pool_b, nullptr, cat, 0, 0);

    // LN3 output rounded (fc1 GEMM A)
    ln_kernel<<<dim3(CAT_, B_), 128>>>(cat, h3, n3w, n3b, CAT_, CAT_, CAT_, 1, nullptr, nullptr);

    tgemm_kernel<0,0><<<dim3(HID_ / 64, (CROWS + 127) / 128), 256, TG_SMEM>>>(
        CROWS, HID_, C_, h3, wfc1, fc1_b, nullptr, fc1o, 1, 1);
    tgemm_kernel<0,0><<<dim3(C_ / 64, (CROWS + 127) / 128), 256, TG_SMEM>>>(
        CROWS, C_, HID_, fc1o, wfc2, fc2_b, nullptr, out, 0, 0);
}